// round 4
// baseline (speedup 1.0000x reference)
#include <cuda_runtime.h>
#include <cuda_fp16.h>
#include <cstdint>

#define DIM      512
#define NLAT     128
#define NTOK     16
#define NBATCH   1024
#define NH       8
#define DH       64
#define M_KV     (NBATCH*NLAT)   // 131072
#define M_Q      (NBATCH*NTOK)   // 16384

// fp16 scratch (device globals: allocation-free)
__device__ __half g_Q[(size_t)M_Q  * DIM];   // 16 MB
__device__ __half g_K[(size_t)M_KV * DIM];   // 128 MB
__device__ __half g_V[(size_t)M_KV * DIM];   // 128 MB
__device__ __half g_A[(size_t)M_Q  * DIM];   // 16 MB

__device__ __forceinline__ uint32_t f2tf32(float x){
    uint32_t u;
    asm("cvt.rna.tf32.f32 %0, %1;" : "=r"(u) : "f"(x));
    return u;
}

__device__ __forceinline__ void mma_tf32(float c[4], const uint32_t a[4], const uint32_t b[2]){
    asm volatile(
        "mma.sync.aligned.m16n8k8.row.col.f32.tf32.tf32.f32 "
        "{%0,%1,%2,%3}, {%4,%5,%6,%7}, {%8,%9}, {%0,%1,%2,%3};\n"
        : "+f"(c[0]), "+f"(c[1]), "+f"(c[2]), "+f"(c[3])
        : "r"(a[0]), "r"(a[1]), "r"(a[2]), "r"(a[3]), "r"(b[0]), "r"(b[1]));
}

#define BM 64
#define BN 64
#define BK 32
#define LDSA (BK + 4)

// C[M,512] = tf32(X[M,512]) @ tf32(W[512,512])^T   (K-dim hardcoded to 512)
// MODE 0: Q proj   (X = x,   out = g_Q fp16)
// MODE 1: K proj   (X = l,   out = g_K fp16, masked-tile skip)
// MODE 2: V proj   (X = l,   out = g_V fp16, masked-tile skip)
// MODE 3: out proj (X = g_A fp16 (implicit), out = fp32 + bias)
template<int MODE>
__global__ __launch_bounds__(128)
void gemm512(const float* __restrict__ X, const float* __restrict__ W,
             const float* __restrict__ bias, float* __restrict__ outf)
{
    const int m0 = blockIdx.y * BM;
    const int n0 = blockIdx.x * BN;

    if (MODE == 1 || MODE == 2) {
        // tile spans latents [m0&127, m0&127 + 63] of batch b = m0>>7.
        // latent j only attended when j <= (b mod 128): skip fully-masked tiles.
        const int bb = m0 >> 7;
        const int jstart = m0 & (NLAT - 1);
        if (jstart > (bb & (NLAT - 1))) return;
    }

    __shared__ float As[2][BM][LDSA];
    __shared__ float Bs[2][BN][LDSA];

    const int tid  = threadIdx.x;
    const int lane = tid & 31;
    const int warp = tid >> 5;
    const int wm   = (warp >> 1) * 32;   // warp row offset in tile
    const int wn   = (warp & 1)  * 32;   // warp col offset in tile

    float c[2][4][4];
    #pragma unroll
    for (int mi = 0; mi < 2; mi++)
        #pragma unroll
        for (int ni = 0; ni < 4; ni++)
            #pragma unroll
            for (int q = 0; q < 4; q++) c[mi][ni][q] = 0.f;

    float4 ra[4], rb[4];

    auto gload = [&](int kt){
        const int k0 = kt * BK;
        #pragma unroll
        for (int p = 0; p < 4; p++){
            const int idx = tid + p * 128;
            const int r  = idx >> 3;
            const int c4 = (idx & 7) * 4;
            if (MODE == 3){
                const __half* src = &g_A[(size_t)(m0 + r) * DIM + k0 + c4];
                uint2 u = *reinterpret_cast<const uint2*>(src);
                __half2 h0 = *reinterpret_cast<__half2*>(&u.x);
                __half2 h1 = *reinterpret_cast<__half2*>(&u.y);
                float2 f0 = __half22float2(h0), f1 = __half22float2(h1);
                ra[p] = make_float4(f0.x, f0.y, f1.x, f1.y);
            } else {
                ra[p] = *reinterpret_cast<const float4*>(&X[(size_t)(m0 + r) * DIM + k0 + c4]);
            }
            rb[p] = *reinterpret_cast<const float4*>(&W[(size_t)(n0 + r) * DIM + k0 + c4]);
        }
    };

    auto sstore = [&](int buf){
        #pragma unroll
        for (int p = 0; p < 4; p++){
            const int idx = tid + p * 128;
            const int r  = idx >> 3;
            const int c4 = (idx & 7) * 4;
            float4 a = ra[p], b = rb[p];
            float4 ta = make_float4(__uint_as_float(f2tf32(a.x)), __uint_as_float(f2tf32(a.y)),
                                    __uint_as_float(f2tf32(a.z)), __uint_as_float(f2tf32(a.w)));
            float4 tb = make_float4(__uint_as_float(f2tf32(b.x)), __uint_as_float(f2tf32(b.y)),
                                    __uint_as_float(f2tf32(b.z)), __uint_as_float(f2tf32(b.w)));
            *reinterpret_cast<float4*>(&As[buf][r][c4]) = ta;
            *reinterpret_cast<float4*>(&Bs[buf][r][c4]) = tb;
        }
    };

    auto compute = [&](int buf){
        #pragma unroll
        for (int ks = 0; ks < 4; ks++){
            const int k = ks * 8;
            uint32_t a[2][4], b[4][2];
            #pragma unroll
            for (int mi = 0; mi < 2; mi++){
                const int rr = wm + mi * 16 + (lane >> 2);
                const int kc = k + (lane & 3);
                a[mi][0] = __float_as_uint(As[buf][rr    ][kc    ]);
                a[mi][1] = __float_as_uint(As[buf][rr + 8][kc    ]);
                a[mi][2] = __float_as_uint(As[buf][rr    ][kc + 4]);
                a[mi][3] = __float_as_uint(As[buf][rr + 8][kc + 4]);
            }
            #pragma unroll
            for (int ni = 0; ni < 4; ni++){
                const int nn = wn + ni * 8 + (lane >> 2);
                const int kc = k + (lane & 3);
                b[ni][0] = __float_as_uint(Bs[buf][nn][kc    ]);
                b[ni][1] = __float_as_uint(Bs[buf][nn][kc + 4]);
            }
            #pragma unroll
            for (int mi = 0; mi < 2; mi++)
                #pragma unroll
                for (int ni = 0; ni < 4; ni++)
                    mma_tf32(c[mi][ni], a[mi], b[ni]);
        }
    };

    gload(0);
    sstore(0);
    __syncthreads();

    int buf = 0;
    #pragma unroll 1
    for (int kt = 0; kt < DIM / BK; ++kt){
        const bool more = (kt + 1 < DIM / BK);
        if (more) gload(kt + 1);
        compute(buf);
        if (more) sstore(buf ^ 1);
        __syncthreads();
        buf ^= 1;
    }

    // epilogue
    #pragma unroll
    for (int mi = 0; mi < 2; mi++){
        #pragma unroll
        for (int ni = 0; ni < 4; ni++){
            const int row = m0 + wm + mi * 16 + (lane >> 2);
            const int col = n0 + wn + ni * 8 + (lane & 3) * 2;
            if (MODE == 3){
                float2 bv = *reinterpret_cast<const float2*>(&bias[col]);
                float2 o0 = make_float2(c[mi][ni][0] + bv.x, c[mi][ni][1] + bv.y);
                float2 o1 = make_float2(c[mi][ni][2] + bv.x, c[mi][ni][3] + bv.y);
                *reinterpret_cast<float2*>(&outf[(size_t)row * DIM + col])       = o0;
                *reinterpret_cast<float2*>(&outf[(size_t)(row + 8) * DIM + col]) = o1;
            } else {
                __half* dst = (MODE == 0) ? g_Q : (MODE == 1) ? g_K : g_V;
                __half2 h0 = __floats2half2_rn(c[mi][ni][0], c[mi][ni][1]);
                __half2 h1 = __floats2half2_rn(c[mi][ni][2], c[mi][ni][3]);
                *reinterpret_cast<__half2*>(&dst[(size_t)row * DIM + col])       = h0;
                *reinterpret_cast<__half2*>(&dst[(size_t)(row + 8) * DIM + col]) = h1;
            }
        }
    }
}

// One block per (head h, batch b). fp32 math from fp16 SMEM tiles.
__global__ __launch_bounds__(128)
void attn_kernel()
{
    const int h = blockIdx.x;
    const int b = blockIdx.y;
    const int rowlim = b & (NLAT - 1);
    const int L = rowlim + 1;
    const int tid = threadIdx.x;

    __shared__ __half Qs[NTOK * DH];
    __shared__ __half Ks[NLAT * (DH + 2)];
    __shared__ __half Vs[NLAT * (DH + 2)];
    __shared__ float  Sc[NTOK * NLAT];
    __shared__ float  Rinv[NTOK];

    for (int idx = tid; idx < NTOK * DH; idx += 128){
        const int i = idx >> 6, d = idx & 63;
        Qs[i * DH + d] = g_Q[(size_t)(b * NTOK + i) * DIM + h * DH + d];
    }
    for (int idx = tid; idx < L * DH; idx += 128){
        const int j = idx >> 6, d = idx & 63;
        const size_t g = (size_t)(b * NLAT + j) * DIM + h * DH + d;
        Ks[j * (DH + 2) + d] = g_K[g];
        Vs[j * (DH + 2) + d] = g_V[g];
    }
    __syncthreads();

    // scores: thread = latent j, loop over the 16 query tokens
    const int j = tid;
    if (j < L){
        #pragma unroll 1
        for (int i = 0; i < NTOK; ++i){
            float s = 0.f;
            #pragma unroll
            for (int d = 0; d < DH; d += 2){
                float2 q = __half22float2(*reinterpret_cast<const __half2*>(&Qs[i * DH + d]));
                float2 k = __half22float2(*reinterpret_cast<const __half2*>(&Ks[j * (DH + 2) + d]));
                s = fmaf(q.x, k.x, s);
                s = fmaf(q.y, k.y, s);
            }
            Sc[i * NLAT + j] = s * 0.125f;   // dh^-0.5 = 1/8
        }
    }
    __syncthreads();

    // softmax per row: store unnormalized exp back, keep 1/sum
    const int warp = tid >> 5, lane = tid & 31;
    for (int i = warp; i < NTOK; i += 4){
        float m = -1e30f;
        for (int jj = lane; jj < L; jj += 32) m = fmaxf(m, Sc[i * NLAT + jj]);
        #pragma unroll
        for (int o = 16; o > 0; o >>= 1) m = fmaxf(m, __shfl_xor_sync(0xffffffffu, m, o));
        float sum = 0.f;
        for (int jj = lane; jj < L; jj += 32){
            const float e = __expf(Sc[i * NLAT + jj] - m);
            Sc[i * NLAT + jj] = e;
            sum += e;
        }
        #pragma unroll
        for (int o = 16; o > 0; o >>= 1) sum += __shfl_xor_sync(0xffffffffu, sum, o);
        if (lane == 0) Rinv[i] = 1.f / sum;
    }
    __syncthreads();

    // attn @ V
    for (int idx = tid; idx < NTOK * DH; idx += 128){
        const int i = idx >> 6, d = idx & 63;
        float acc = 0.f;
        #pragma unroll 4
        for (int jj = 0; jj < L; ++jj)
            acc = fmaf(Sc[i * NLAT + jj], __half2float(Vs[jj * (DH + 2) + d]), acc);
        g_A[(size_t)(b * NTOK + i) * DIM + h * DH + d] = __float2half_rn(acc * Rinv[i]);
    }
}

extern "C" void kernel_launch(void* const* d_in, const int* in_sizes, int n_in,
                              void* d_out, int out_size)
{
    (void)in_sizes; (void)n_in; (void)out_size;
    const float* x  = (const float*)d_in[0];
    const float* l  = (const float*)d_in[1];
    const float* Wq = (const float*)d_in[2];
    const float* Wk = (const float*)d_in[3];
    const float* Wv = (const float*)d_in[4];
    const float* Wo = (const float*)d_in[5];
    const float* bo = (const float*)d_in[6];
    float* out = (float*)d_out;

    const dim3 blk(128);
    gemm512<0><<<dim3(DIM / BN, M_Q  / BM), blk>>>(x, Wq, nullptr, nullptr);
    gemm512<1><<<dim3(DIM / BN, M_KV / BM), blk>>>(l, Wk, nullptr, nullptr);
    gemm512<2><<<dim3(DIM / BN, M_KV / BM), blk>>>(l, Wv, nullptr, nullptr);
    attn_kernel<<<dim3(NH, NBATCH), blk>>>();
    gemm512<3><<<dim3(DIM / BN, M_Q  / BM), blk>>>(nullptr, Wo, bo, out);
}

// round 5
// speedup vs baseline: 1.1576x; 1.1576x over previous
#include <cuda_runtime.h>
#include <cuda_fp16.h>
#include <cstdint>

#define DIM      512
#define NLAT     128
#define NTOK     16
#define NBATCH   1024
#define NH       8
#define DH       64
#define M_KV     (NBATCH*NLAT)   // 131072
#define M_Q      (NBATCH*NTOK)   // 16384

// fp16 scratch (device globals: allocation-free)
__device__ __half g_Q[(size_t)M_Q  * DIM];   // 16 MB
__device__ __half g_K[(size_t)M_KV * DIM];   // 128 MB
__device__ __half g_V[(size_t)M_KV * DIM];   // 128 MB
__device__ __half g_A[(size_t)M_Q  * DIM];   // 16 MB

__device__ __forceinline__ uint32_t f2tf32(float x){
    uint32_t u;
    asm("cvt.rna.tf32.f32 %0, %1;" : "=r"(u) : "f"(x));
    return u;
}

__device__ __forceinline__ void mma_tf32(float c[4], const uint32_t a[4], const uint32_t b[2]){
    asm volatile(
        "mma.sync.aligned.m16n8k8.row.col.f32.tf32.tf32.f32 "
        "{%0,%1,%2,%3}, {%4,%5,%6,%7}, {%8,%9}, {%0,%1,%2,%3};\n"
        : "+f"(c[0]), "+f"(c[1]), "+f"(c[2]), "+f"(c[3])
        : "r"(a[0]), "r"(a[1]), "r"(a[2]), "r"(a[3]), "r"(b[0]), "r"(b[1]));
}

#define BM 64
#define BN 128
#define BK 32
#define LDSA (BK + 4)

// C[M,512] = tf32(X[M,512]) @ tf32(W[512,512])^T   (K-dim hardcoded to 512)
// MODE 0: Q proj   (X = x,   out = g_Q fp16)
// MODE 1: K proj   (X = l,   out = g_K fp16, masked-tile skip)
// MODE 2: V proj   (X = l,   out = g_V fp16, masked-tile skip)
// MODE 3: out proj (X = g_A fp16 (implicit), out = fp32 + bias)
template<int MODE>
__global__ __launch_bounds__(128, 3)
void gemm512(const float* __restrict__ X, const float* __restrict__ W,
             const float* __restrict__ bias, float* __restrict__ outf)
{
    const int m0 = blockIdx.y * BM;
    const int n0 = blockIdx.x * BN;

    if (MODE == 1 || MODE == 2) {
        // latent j only attended when j <= (b mod 128): skip fully-masked tiles.
        const int bb = m0 >> 7;
        const int jstart = m0 & (NLAT - 1);
        if (jstart > (bb & (NLAT - 1))) return;
    }

    __shared__ float As[2][BM][LDSA];
    __shared__ float Bs[2][BN][LDSA];

    const int tid  = threadIdx.x;
    const int lane = tid & 31;
    const int warp = tid >> 5;
    const int wm   = (warp >> 1) * 32;   // warp row offset (0/32)
    const int wn   = (warp & 1)  * 64;   // warp col offset (0/64)

    float c[2][8][4];
    #pragma unroll
    for (int mi = 0; mi < 2; mi++)
        #pragma unroll
        for (int ni = 0; ni < 8; ni++)
            #pragma unroll
            for (int q = 0; q < 4; q++) c[mi][ni][q] = 0.f;

    float4 ra[4], rb[8];

    auto gload = [&](int kt){
        const int k0 = kt * BK;
        #pragma unroll
        for (int p = 0; p < 4; p++){   // A: 64 rows x 32 = 512 float4
            const int idx = tid + p * 128;
            const int r  = idx >> 3;
            const int c4 = (idx & 7) * 4;
            if (MODE == 3){
                const __half* src = &g_A[(size_t)(m0 + r) * DIM + k0 + c4];
                uint2 u = *reinterpret_cast<const uint2*>(src);
                __half2 h0 = *reinterpret_cast<__half2*>(&u.x);
                __half2 h1 = *reinterpret_cast<__half2*>(&u.y);
                float2 f0 = __half22float2(h0), f1 = __half22float2(h1);
                ra[p] = make_float4(f0.x, f0.y, f1.x, f1.y);
            } else {
                ra[p] = *reinterpret_cast<const float4*>(&X[(size_t)(m0 + r) * DIM + k0 + c4]);
            }
        }
        #pragma unroll
        for (int p = 0; p < 8; p++){   // B: 128 rows x 32 = 1024 float4
            const int idx = tid + p * 128;
            const int r  = idx >> 3;
            const int c4 = (idx & 7) * 4;
            rb[p] = *reinterpret_cast<const float4*>(&W[(size_t)(n0 + r) * DIM + k0 + c4]);
        }
    };

    auto cvt4 = [](float4 v){
        return make_float4(__uint_as_float(f2tf32(v.x)), __uint_as_float(f2tf32(v.y)),
                           __uint_as_float(f2tf32(v.z)), __uint_as_float(f2tf32(v.w)));
    };

    auto sstore = [&](int buf){
        #pragma unroll
        for (int p = 0; p < 4; p++){
            const int idx = tid + p * 128;
            *reinterpret_cast<float4*>(&As[buf][idx >> 3][(idx & 7) * 4]) = cvt4(ra[p]);
        }
        #pragma unroll
        for (int p = 0; p < 8; p++){
            const int idx = tid + p * 128;
            *reinterpret_cast<float4*>(&Bs[buf][idx >> 3][(idx & 7) * 4]) = cvt4(rb[p]);
        }
    };

    auto compute = [&](int buf){
        #pragma unroll
        for (int ks = 0; ks < 4; ks++){
            const int k = ks * 8;
            const int kc = k + (lane & 3);
            uint32_t a[2][4], b[8][2];
            #pragma unroll
            for (int mi = 0; mi < 2; mi++){
                const int rr = wm + mi * 16 + (lane >> 2);
                a[mi][0] = __float_as_uint(As[buf][rr    ][kc    ]);
                a[mi][1] = __float_as_uint(As[buf][rr + 8][kc    ]);
                a[mi][2] = __float_as_uint(As[buf][rr    ][kc + 4]);
                a[mi][3] = __float_as_uint(As[buf][rr + 8][kc + 4]);
            }
            #pragma unroll
            for (int ni = 0; ni < 8; ni++){
                const int nn = wn + ni * 8 + (lane >> 2);
                b[ni][0] = __float_as_uint(Bs[buf][nn][kc    ]);
                b[ni][1] = __float_as_uint(Bs[buf][nn][kc + 4]);
            }
            #pragma unroll
            for (int mi = 0; mi < 2; mi++)
                #pragma unroll
                for (int ni = 0; ni < 8; ni++)
                    mma_tf32(c[mi][ni], a[mi], b[ni]);
        }
    };

    gload(0);
    sstore(0);
    __syncthreads();

    int buf = 0;
    #pragma unroll 1
    for (int kt = 0; kt < DIM / BK; ++kt){
        const bool more = (kt + 1 < DIM / BK);
        if (more) gload(kt + 1);
        compute(buf);
        if (more) sstore(buf ^ 1);
        __syncthreads();
        buf ^= 1;
    }

    // epilogue
    #pragma unroll
    for (int mi = 0; mi < 2; mi++){
        #pragma unroll
        for (int ni = 0; ni < 8; ni++){
            const int row = m0 + wm + mi * 16 + (lane >> 2);
            const int col = n0 + wn + ni * 8 + (lane & 3) * 2;
            if (MODE == 3){
                float2 bv = *reinterpret_cast<const float2*>(&bias[col]);
                float2 o0 = make_float2(c[mi][ni][0] + bv.x, c[mi][ni][1] + bv.y);
                float2 o1 = make_float2(c[mi][ni][2] + bv.x, c[mi][ni][3] + bv.y);
                *reinterpret_cast<float2*>(&outf[(size_t)row * DIM + col])       = o0;
                *reinterpret_cast<float2*>(&outf[(size_t)(row + 8) * DIM + col]) = o1;
            } else {
                __half* dst = (MODE == 0) ? g_Q : (MODE == 1) ? g_K : g_V;
                __half2 h0 = __floats2half2_rn(c[mi][ni][0], c[mi][ni][1]);
                __half2 h1 = __floats2half2_rn(c[mi][ni][2], c[mi][ni][3]);
                *reinterpret_cast<__half2*>(&dst[(size_t)row * DIM + col])       = h0;
                *reinterpret_cast<__half2*>(&dst[(size_t)(row + 8) * DIM + col]) = h1;
            }
        }
    }
}

// One block per (head h, batch b).
#define PLD 132   // padded row stride (halves) for P
__global__ __launch_bounds__(128, 8)
void attn_kernel()
{
    const int h = blockIdx.x;
    const int b = blockIdx.y;
    const int rowlim = b & (NLAT - 1);
    const int L = rowlim + 1;
    const int tid = threadIdx.x;

    __shared__ __half2 Qs[NTOK * 33];    // [16][33] half2, padded
    __shared__ __half2 Ks[NLAT * 33];    // [128][33] half2, padded
    __shared__ __half  P [NTOK * PLD];   // fp16 scores -> unnormalized probs
    __shared__ float   Rinv[NTOK];

    const __half2* Q2 = reinterpret_cast<const __half2*>(g_Q);
    const __half2* K2 = reinterpret_cast<const __half2*>(g_K);
    const __half2* V2 = reinterpret_cast<const __half2*>(g_V);
    __half2* A2 = reinterpret_cast<__half2*>(g_A);

    // loads (coalesced)
    for (int idx = tid; idx < NTOK * 32; idx += 128){
        const int i = idx >> 5, d2 = idx & 31;
        Qs[i * 33 + d2] = Q2[(size_t)(b * NTOK + i) * 256 + h * 32 + d2];
    }
    for (int idx = tid; idx < L * 32; idx += 128){
        const int j = idx >> 5, d2 = idx & 31;
        Ks[j * 33 + d2] = K2[(size_t)(b * NLAT + j) * 256 + h * 32 + d2];
    }
    __syncthreads();

    // scores: flatten all L*16 dot products over 128 threads
    for (int w = tid; w < L * NTOK; w += 128){
        const int j = w >> 4;
        const int i = w & 15;
        float s = 0.f;
        #pragma unroll
        for (int d2 = 0; d2 < 32; ++d2){
            float2 q = __half22float2(Qs[i * 33 + d2]);
            float2 k = __half22float2(Ks[j * 33 + d2]);
            s = fmaf(q.x, k.x, s);
            s = fmaf(q.y, k.y, s);
        }
        P[i * PLD + j] = __float2half(s * 0.125f);   // dh^-0.5 = 1/8
    }
    __syncthreads();

    // softmax per row (warp per row, 4 rows/warp)
    const int warp = tid >> 5, lane = tid & 31;
    for (int i = warp; i < NTOK; i += 4){
        float m = -1e30f;
        for (int jj = lane; jj < L; jj += 32) m = fmaxf(m, __half2float(P[i * PLD + jj]));
        #pragma unroll
        for (int o = 16; o > 0; o >>= 1) m = fmaxf(m, __shfl_xor_sync(0xffffffffu, m, o));
        float sum = 0.f;
        for (int jj = lane; jj < L; jj += 32){
            const float e = __expf(__half2float(P[i * PLD + jj]) - m);
            P[i * PLD + jj] = __float2half(e);
            sum += e;
        }
        #pragma unroll
        for (int o = 16; o > 0; o >>= 1) sum += __shfl_xor_sync(0xffffffffu, sum, o);
        if (lane == 0) Rinv[i] = 1.f / sum;
    }
    __syncthreads();

    // attn @ V : thread = (warp ig -> 4 query rows, lane -> half2 column)
    const int ig = tid >> 5;
    const int d2 = tid & 31;
    float acc[4][2];
    #pragma unroll
    for (int r = 0; r < 4; r++){ acc[r][0] = 0.f; acc[r][1] = 0.f; }

    const __half2* vptr = &V2[(size_t)(b * NLAT) * 256 + h * 32 + d2];
    #pragma unroll 2
    for (int jj = 0; jj < L; ++jj){
        float2 v = __half22float2(__ldg(vptr + (size_t)jj * 256));
        #pragma unroll
        for (int r = 0; r < 4; r++){
            const float p = __half2float(P[(ig * 4 + r) * PLD + jj]);
            acc[r][0] = fmaf(p, v.x, acc[r][0]);
            acc[r][1] = fmaf(p, v.y, acc[r][1]);
        }
    }
    #pragma unroll
    for (int r = 0; r < 4; r++){
        const int i = ig * 4 + r;
        const float ri = Rinv[i];
        A2[(size_t)(b * NTOK + i) * 256 + h * 32 + d2] =
            __floats2half2_rn(acc[r][0] * ri, acc[r][1] * ri);
    }
}

extern "C" void kernel_launch(void* const* d_in, const int* in_sizes, int n_in,
                              void* d_out, int out_size)
{
    (void)in_sizes; (void)n_in; (void)out_size;
    const float* x  = (const float*)d_in[0];
    const float* l  = (const float*)d_in[1];
    const float* Wq = (const float*)d_in[2];
    const float* Wk = (const float*)d_in[3];
    const float* Wv = (const float*)d_in[4];
    const float* Wo = (const float*)d_in[5];
    const float* bo = (const float*)d_in[6];
    float* out = (float*)d_out;

    const dim3 blk(128);
    gemm512<0><<<dim3(DIM / BN, M_Q  / BM), blk>>>(x, Wq, nullptr, nullptr);
    gemm512<1><<<dim3(DIM / BN, M_KV / BM), blk>>>(l, Wk, nullptr, nullptr);
    gemm512<2><<<dim3(DIM / BN, M_KV / BM), blk>>>(l, Wv, nullptr, nullptr);
    attn_kernel<<<dim3(NH, NBATCH), blk>>>();
    gemm512<3><<<dim3(DIM / BN, M_Q  / BM), blk>>>(nullptr, Wo, bo, out);
}

// round 6
// speedup vs baseline: 1.8870x; 1.6301x over previous
#include <cuda_runtime.h>
#include <cuda_fp16.h>
#include <cstdint>

#define DIM      512
#define NLAT     128
#define NTOK     16
#define NBATCH   1024
#define NH       8
#define DH       64
#define M_KV     (NBATCH*NLAT)   // 131072
#define M_Q      (NBATCH*NTOK)   // 16384

// fp16 scratch (device globals: allocation-free, zero-initialized)
__device__ __half g_Q  [(size_t)M_Q  * DIM];   // 16 MB
__device__ __half g_K  [(size_t)M_KV * DIM];   // 128 MB
__device__ __half g_V  [(size_t)M_KV * DIM];   // 128 MB
__device__ __half g_A  [(size_t)M_Q  * DIM];   // 16 MB
__device__ __half g_x16[(size_t)M_Q  * DIM];   // 16 MB
__device__ __half g_l16[(size_t)M_KV * DIM];   // 128 MB
__device__ __half g_W16[4 * DIM * DIM];        // 2 MB

// ---------------- fp32 -> fp16 conversion pass ----------------
// which: 0 = x -> g_x16, 1 = l -> g_l16 (mask-skipped rows stay 0),
//        2..5 = Wq/Wk/Wv/Wo -> g_W16 slices
__global__ __launch_bounds__(256)
void f2h_kernel(const float4* __restrict__ in, int n4, int which)
{
    const int i = blockIdx.x * 256 + threadIdx.x;
    if (i >= n4) return;
    if (which == 1){
        const int row = i >> 7;                 // 128 float4 per 512-row
        if ((row & 127) > ((row >> 7) & 127)) return;   // latent never attended
    }
    __half2* out = (which == 0) ? reinterpret_cast<__half2*>(g_x16)
                 : (which == 1) ? reinterpret_cast<__half2*>(g_l16)
                 : reinterpret_cast<__half2*>(g_W16 + (size_t)(which - 2) * DIM * DIM);
    const float4 v = in[i];
    out[2 * i    ] = __floats2half2_rn(v.x, v.y);
    out[2 * i + 1] = __floats2half2_rn(v.z, v.w);
}

// ---------------- fp16 tensor-core GEMM ----------------
__device__ __forceinline__ void cpa16(uint32_t s, const void* g){
    asm volatile("cp.async.cg.shared.global [%0], [%1], 16;\n" :: "r"(s), "l"(g));
}
__device__ __forceinline__ void ldsm4(uint32_t& r0, uint32_t& r1, uint32_t& r2, uint32_t& r3,
                                      uint32_t addr){
    asm volatile("ldmatrix.sync.aligned.m8n8.x4.shared.b16 {%0,%1,%2,%3}, [%4];\n"
                 : "=r"(r0), "=r"(r1), "=r"(r2), "=r"(r3) : "r"(addr));
}
__device__ __forceinline__ void mma_f16(float c[4], const uint32_t a[4],
                                        uint32_t b0, uint32_t b1){
    asm volatile(
        "mma.sync.aligned.m16n8k16.row.col.f32.f16.f16.f32 "
        "{%0,%1,%2,%3}, {%4,%5,%6,%7}, {%8,%9}, {%0,%1,%2,%3};\n"
        : "+f"(c[0]), "+f"(c[1]), "+f"(c[2]), "+f"(c[3])
        : "r"(a[0]), "r"(a[1]), "r"(a[2]), "r"(a[3]), "r"(b0), "r"(b1));
}

#define BM 64
#define BN 128
#define BK 64
#define AST   72                 // half stride per smem row (144 B: 16B-aligned, LDSM conflict-free)
#define A_BUF (BM * AST)         // 4608 halves
#define B_BUF (BN * AST)         // 9216 halves
#define GEMM_SMEM_BYTES ((2 * A_BUF + 2 * B_BUF) * 2)   // 55296 B

// C[M,512] = fp16(X) @ fp16(W)^T, fp32 accumulate.
// MODE 0: Q proj (A=g_x16 -> g_Q)   1: K proj (A=g_l16 -> g_K, tile skip)
// MODE 2: V proj (A=g_l16 -> g_V)   3: out proj (A=g_A -> fp32 out + bias)
template<int MODE>
__global__ __launch_bounds__(128, 4)
void gemm512(const float* __restrict__ bias, float* __restrict__ outf)
{
    const int m0 = blockIdx.y * BM;
    const int n0 = blockIdx.x * BN;

    if (MODE == 1 || MODE == 2){
        const int bb = m0 >> 7;
        const int jstart = m0 & (NLAT - 1);
        if (jstart > (bb & (NLAT - 1))) return;   // fully-masked latent tile
    }

    const __half* __restrict__ Asrc =
        (MODE == 0) ? g_x16 : (MODE == 3) ? g_A : g_l16;
    const __half* __restrict__ Wsrc = g_W16 + (size_t)MODE * DIM * DIM;

    extern __shared__ __half sh[];
    const uint32_t sbase = (uint32_t)__cvta_generic_to_shared(sh);

    const int tid  = threadIdx.x;
    const int lane = tid & 31;
    const int warp = tid >> 5;
    const int wm   = (warp >> 1) * 32;   // 0/32
    const int wn   = (warp & 1)  * 64;   // 0/64

    float c[2][8][4];
    #pragma unroll
    for (int mi = 0; mi < 2; mi++)
        #pragma unroll
        for (int ni = 0; ni < 8; ni++)
            #pragma unroll
            for (int q = 0; q < 4; q++) c[mi][ni][q] = 0.f;

    auto gload = [&](int kt, int buf){
        const int k0 = kt * BK;
        #pragma unroll
        for (int p = 0; p < 4; p++){            // A: 64 rows x 8 chunks
            const int id = tid + p * 128;
            const int r = id >> 3, ck = (id & 7) * 8;
            cpa16(sbase + 2u * (buf * A_BUF + r * AST + ck),
                  Asrc + (size_t)(m0 + r) * DIM + k0 + ck);
        }
        #pragma unroll
        for (int p = 0; p < 8; p++){            // B: 128 rows x 8 chunks
            const int id = tid + p * 128;
            const int r = id >> 3, ck = (id & 7) * 8;
            cpa16(sbase + 2u * (2 * A_BUF + buf * B_BUF + r * AST + ck),
                  Wsrc + (size_t)(n0 + r) * DIM + k0 + ck);
        }
        asm volatile("cp.async.commit_group;\n");
    };

    const int lrow = (lane & 7) + ((lane >> 3) & 1) * 8;   // ldmatrix row-in-16
    const int lksel = (lane & 16) ? 8 : 0;                 // ldmatrix k-half select

    auto compute = [&](int buf){
        const uint32_t aoff = buf * A_BUF;
        const uint32_t boff = 2 * A_BUF + buf * B_BUF;
        #pragma unroll
        for (int ks = 0; ks < 4; ks++){
            const int kk = ks * 16 + lksel;
            uint32_t a[2][4], bb[4][4];
            #pragma unroll
            for (int mi = 0; mi < 2; mi++){
                const int row = wm + mi * 16 + lrow;
                ldsm4(a[mi][0], a[mi][1], a[mi][2], a[mi][3],
                      sbase + 2u * (aoff + row * AST + kk));
            }
            #pragma unroll
            for (int nip = 0; nip < 4; nip++){
                const int nrow = wn + nip * 16 + lrow;
                ldsm4(bb[nip][0], bb[nip][1], bb[nip][2], bb[nip][3],
                      sbase + 2u * (boff + nrow * AST + kk));
            }
            #pragma unroll
            for (int mi = 0; mi < 2; mi++)
                #pragma unroll
                for (int nip = 0; nip < 4; nip++){
                    mma_f16(c[mi][2 * nip    ], a[mi], bb[nip][0], bb[nip][2]);
                    mma_f16(c[mi][2 * nip + 1], a[mi], bb[nip][1], bb[nip][3]);
                }
        }
    };

    gload(0, 0);
    int buf = 0;
    #pragma unroll 1
    for (int kt = 0; kt < DIM / BK; ++kt){
        const bool more = (kt + 1 < DIM / BK);
        if (more) gload(kt + 1, buf ^ 1);
        if (more) { asm volatile("cp.async.wait_group 1;\n"); }
        else      { asm volatile("cp.async.wait_group 0;\n"); }
        __syncthreads();
        compute(buf);
        __syncthreads();
        buf ^= 1;
    }

    // epilogue
    #pragma unroll
    for (int mi = 0; mi < 2; mi++){
        #pragma unroll
        for (int ni = 0; ni < 8; ni++){
            const int row = m0 + wm + mi * 16 + (lane >> 2);
            const int col = n0 + wn + ni * 8 + (lane & 3) * 2;
            if (MODE == 3){
                float2 bv = *reinterpret_cast<const float2*>(&bias[col]);
                float2 o0 = make_float2(c[mi][ni][0] + bv.x, c[mi][ni][1] + bv.y);
                float2 o1 = make_float2(c[mi][ni][2] + bv.x, c[mi][ni][3] + bv.y);
                *reinterpret_cast<float2*>(&outf[(size_t)row * DIM + col])       = o0;
                *reinterpret_cast<float2*>(&outf[(size_t)(row + 8) * DIM + col]) = o1;
            } else {
                __half* dst = (MODE == 0) ? g_Q : (MODE == 1) ? g_K : g_V;
                __half2 h0 = __floats2half2_rn(c[mi][ni][0], c[mi][ni][1]);
                __half2 h1 = __floats2half2_rn(c[mi][ni][2], c[mi][ni][3]);
                *reinterpret_cast<__half2*>(&dst[(size_t)row * DIM + col])       = h0;
                *reinterpret_cast<__half2*>(&dst[(size_t)(row + 8) * DIM + col]) = h1;
            }
        }
    }
}

// ---------------- attention ----------------
#define PLD 132   // padded row stride (halves) for P
__global__ __launch_bounds__(128, 8)
void attn_kernel()
{
    const int h = blockIdx.x;
    const int b = blockIdx.y;
    const int L = (b & (NLAT - 1)) + 1;
    const int tid = threadIdx.x;

    __shared__ __half2 Qs[NTOK * 33];
    __shared__ __half2 Ks[NLAT * 33];
    __shared__ __half  P [NTOK * PLD];
    __shared__ float   Rinv[NTOK];

    const __half2* Q2 = reinterpret_cast<const __half2*>(g_Q);
    const __half2* K2 = reinterpret_cast<const __half2*>(g_K);
    const __half2* V2 = reinterpret_cast<const __half2*>(g_V);
    __half2* A2 = reinterpret_cast<__half2*>(g_A);

    for (int idx = tid; idx < NTOK * 32; idx += 128){
        const int i = idx >> 5, d2 = idx & 31;
        Qs[i * 33 + d2] = Q2[(size_t)(b * NTOK + i) * 256 + h * 32 + d2];
    }
    for (int idx = tid; idx < L * 32; idx += 128){
        const int j = idx >> 5, d2 = idx & 31;
        Ks[j * 33 + d2] = K2[(size_t)(b * NLAT + j) * 256 + h * 32 + d2];
    }
    __syncthreads();

    // scores: all L*16 dots over 128 threads, 4 independent accumulators
    for (int w = tid; w < L * NTOK; w += 128){
        const int j = w >> 4;
        const int i = w & 15;
        float s0 = 0.f, s1 = 0.f, s2 = 0.f, s3 = 0.f;
        #pragma unroll
        for (int d2 = 0; d2 < 32; d2 += 4){
            float2 q0 = __half22float2(Qs[i * 33 + d2    ]);
            float2 k0 = __half22float2(Ks[j * 33 + d2    ]);
            float2 q1 = __half22float2(Qs[i * 33 + d2 + 1]);
            float2 k1 = __half22float2(Ks[j * 33 + d2 + 1]);
            float2 q2 = __half22float2(Qs[i * 33 + d2 + 2]);
            float2 k2 = __half22float2(Ks[j * 33 + d2 + 2]);
            float2 q3 = __half22float2(Qs[i * 33 + d2 + 3]);
            float2 k3 = __half22float2(Ks[j * 33 + d2 + 3]);
            s0 = fmaf(q0.x, k0.x, s0); s0 = fmaf(q0.y, k0.y, s0);
            s1 = fmaf(q1.x, k1.x, s1); s1 = fmaf(q1.y, k1.y, s1);
            s2 = fmaf(q2.x, k2.x, s2); s2 = fmaf(q2.y, k2.y, s2);
            s3 = fmaf(q3.x, k3.x, s3); s3 = fmaf(q3.y, k3.y, s3);
        }
        P[i * PLD + j] = __float2half(((s0 + s1) + (s2 + s3)) * 0.125f);
    }
    __syncthreads();

    // softmax per row (warp per row)
    const int warp = tid >> 5, lane = tid & 31;
    for (int i = warp; i < NTOK; i += 4){
        float m = -1e30f;
        for (int jj = lane; jj < L; jj += 32) m = fmaxf(m, __half2float(P[i * PLD + jj]));
        #pragma unroll
        for (int o = 16; o > 0; o >>= 1) m = fmaxf(m, __shfl_xor_sync(0xffffffffu, m, o));
        float sum = 0.f;
        for (int jj = lane; jj < L; jj += 32){
            const float e = __expf(__half2float(P[i * PLD + jj]) - m);
            P[i * PLD + jj] = __float2half(e);
            sum += e;
        }
        #pragma unroll
        for (int o = 16; o > 0; o >>= 1) sum += __shfl_xor_sync(0xffffffffu, sum, o);
        if (lane == 0) Rinv[i] = 1.f / sum;
    }
    __syncthreads();

    // attn @ V : warp -> 4 query rows, lane -> half2 column
    const int ig = tid >> 5;
    const int d2 = tid & 31;
    float acc[4][2];
    #pragma unroll
    for (int r = 0; r < 4; r++){ acc[r][0] = 0.f; acc[r][1] = 0.f; }

    const __half2* vptr = &V2[(size_t)(b * NLAT) * 256 + h * 32 + d2];
    #pragma unroll 2
    for (int jj = 0; jj < L; ++jj){
        float2 v = __half22float2(__ldg(vptr + (size_t)jj * 256));
        #pragma unroll
        for (int r = 0; r < 4; r++){
            const float p = __half2float(P[(ig * 4 + r) * PLD + jj]);
            acc[r][0] = fmaf(p, v.x, acc[r][0]);
            acc[r][1] = fmaf(p, v.y, acc[r][1]);
        }
    }
    #pragma unroll
    for (int r = 0; r < 4; r++){
        const int i = ig * 4 + r;
        const float ri = Rinv[i];
        A2[(size_t)(b * NTOK + i) * 256 + h * 32 + d2] =
            __floats2half2_rn(acc[r][0] * ri, acc[r][1] * ri);
    }
}

extern "C" void kernel_launch(void* const* d_in, const int* in_sizes, int n_in,
                              void* d_out, int out_size)
{
    (void)in_sizes; (void)n_in; (void)out_size;
    const float* x  = (const float*)d_in[0];
    const float* l  = (const float*)d_in[1];
    const float* Wq = (const float*)d_in[2];
    const float* Wk = (const float*)d_in[3];
    const float* Wv = (const float*)d_in[4];
    const float* Wo = (const float*)d_in[5];
    const float* bo = (const float*)d_in[6];
    float* out = (float*)d_out;

    static bool attr_done = false;
    if (!attr_done){
        cudaFuncSetAttribute(gemm512<0>, cudaFuncAttributeMaxDynamicSharedMemorySize, GEMM_SMEM_BYTES);
        cudaFuncSetAttribute(gemm512<1>, cudaFuncAttributeMaxDynamicSharedMemorySize, GEMM_SMEM_BYTES);
        cudaFuncSetAttribute(gemm512<2>, cudaFuncAttributeMaxDynamicSharedMemorySize, GEMM_SMEM_BYTES);
        cudaFuncSetAttribute(gemm512<3>, cudaFuncAttributeMaxDynamicSharedMemorySize, GEMM_SMEM_BYTES);
        attr_done = true;
    }

    const dim3 blk(128);
    // fp32 -> fp16 staging
    {
        const int n4x = M_Q  * DIM / 4;   // 2,097,152
        const int n4l = M_KV * DIM / 4;   // 16,777,216
        const int n4w = DIM * DIM / 4;    // 65,536
        f2h_kernel<<<(n4x + 255) / 256, 256>>>((const float4*)x, n4x, 0);
        f2h_kernel<<<(n4l + 255) / 256, 256>>>((const float4*)l, n4l, 1);
        f2h_kernel<<<(n4w + 255) / 256, 256>>>((const float4*)Wq, n4w, 2);
        f2h_kernel<<<(n4w + 255) / 256, 256>>>((const float4*)Wk, n4w, 3);
        f2h_kernel<<<(n4w + 255) / 256, 256>>>((const float4*)Wv, n4w, 4);
        f2h_kernel<<<(n4w + 255) / 256, 256>>>((const float4*)Wo, n4w, 5);
    }

    gemm512<0><<<dim3(DIM / BN, M_Q  / BM), blk, GEMM_SMEM_BYTES>>>(nullptr, nullptr);
    gemm512<1><<<dim3(DIM / BN, M_KV / BM), blk, GEMM_SMEM_BYTES>>>(nullptr, nullptr);
    gemm512<2><<<dim3(DIM / BN, M_KV / BM), blk, GEMM_SMEM_BYTES>>>(nullptr, nullptr);
    attn_kernel<<<dim3(NH, NBATCH), blk>>>();
    gemm512<3><<<dim3(DIM / BN, M_Q  / BM), blk, GEMM_SMEM_BYTES>>>(bo, out);
}

// round 8
// speedup vs baseline: 2.5116x; 1.3310x over previous
#include <cuda_runtime.h>
#include <cuda_fp16.h>
#include <cstdint>

#define DIM      512
#define NLAT     128
#define NTOK     16
#define NBATCH   1024
#define NH       8
#define M_KV     (NBATCH*NLAT)   // 131072
#define M_Q      (NBATCH*NTOK)   // 16384

// fp16 scratch (device globals: allocation-free, zero-initialized)
__device__ __half g_Q  [(size_t)M_Q  * DIM];
__device__ __half g_K  [(size_t)M_KV * DIM];
__device__ __half g_V  [(size_t)M_KV * DIM];
__device__ __half g_A  [(size_t)M_Q  * DIM];
__device__ __half g_x16[(size_t)M_Q  * DIM];
__device__ __half g_l16[(size_t)M_KV * DIM];
__device__ __half g_W16[4 * DIM * DIM];        // Wq, Wk, Wv, Wo

// ---------------- fp32 -> fp16 staging ----------------
__global__ __launch_bounds__(256)
void f2h_kernel(const float4* __restrict__ in, int n4, int which)
{
    const int i = blockIdx.x * 256 + threadIdx.x;
    if (i >= n4) return;
    if (which == 1){
        const int row = i >> 7;
        if ((row & 127) > ((row >> 7) & 127)) return;   // latent never attended
    }
    __half2* out = (which == 0) ? reinterpret_cast<__half2*>(g_x16)
                 : (which == 1) ? reinterpret_cast<__half2*>(g_l16)
                 : reinterpret_cast<__half2*>(g_W16 + (size_t)(which - 2) * DIM * DIM);
    const float4 v = in[i];
    out[2 * i    ] = __floats2half2_rn(v.x, v.y);
    out[2 * i + 1] = __floats2half2_rn(v.z, v.w);
}

// ---------------- mma helpers ----------------
__device__ __forceinline__ void cpa16(uint32_t s, const void* g){
    asm volatile("cp.async.cg.shared.global [%0], [%1], 16;\n" :: "r"(s), "l"(g));
}
__device__ __forceinline__ void ldsm4(uint32_t& r0, uint32_t& r1, uint32_t& r2, uint32_t& r3,
                                      uint32_t addr){
    asm volatile("ldmatrix.sync.aligned.m8n8.x4.shared.b16 {%0,%1,%2,%3}, [%4];\n"
                 : "=r"(r0), "=r"(r1), "=r"(r2), "=r"(r3) : "r"(addr));
}
__device__ __forceinline__ void ldsm4t(uint32_t& r0, uint32_t& r1, uint32_t& r2, uint32_t& r3,
                                       uint32_t addr){
    asm volatile("ldmatrix.sync.aligned.m8n8.x4.trans.shared.b16 {%0,%1,%2,%3}, [%4];\n"
                 : "=r"(r0), "=r"(r1), "=r"(r2), "=r"(r3) : "r"(addr));
}
__device__ __forceinline__ void mma_f16(float c[4], const uint32_t a[4],
                                        uint32_t b0, uint32_t b1){
    asm volatile(
        "mma.sync.aligned.m16n8k16.row.col.f32.f16.f16.f32 "
        "{%0,%1,%2,%3}, {%4,%5,%6,%7}, {%8,%9}, {%0,%1,%2,%3};\n"
        : "+f"(c[0]), "+f"(c[1]), "+f"(c[2]), "+f"(c[3])
        : "r"(a[0]), "r"(a[1]), "r"(a[2]), "r"(a[3]), "r"(b0), "r"(b1));
}

// ---------------- fp16 tensor-core GEMM (round-6 proven) ----------------
#define BM 64
#define BN 128
#define BK 64
#define AST   72
#define A_BUF (BM * AST)
#define B_BUF (BN * AST)
#define GEMM_SMEM_BYTES ((2 * A_BUF + 2 * B_BUF) * 2)   // 55296 B

template<int MODE>
__global__ __launch_bounds__(128, 4)
void gemm512(const float* __restrict__ bias, float* __restrict__ outf)
{
    const int m0 = blockIdx.y * BM;
    const int n0 = blockIdx.x * BN;

    if (MODE == 1 || MODE == 2){
        const int bb = m0 >> 7;
        const int jstart = m0 & (NLAT - 1);
        if (jstart > (bb & (NLAT - 1))) return;
    }

    const __half* __restrict__ Asrc =
        (MODE == 0) ? g_x16 : (MODE == 3) ? g_A : g_l16;
    const __half* __restrict__ Wsrc = g_W16 + (size_t)MODE * DIM * DIM;

    extern __shared__ __half sh[];
    const uint32_t sbase = (uint32_t)__cvta_generic_to_shared(sh);

    const int tid  = threadIdx.x;
    const int lane = tid & 31;
    const int warp = tid >> 5;
    const int wm   = (warp >> 1) * 32;
    const int wn   = (warp & 1)  * 64;

    float c[2][8][4];
    #pragma unroll
    for (int mi = 0; mi < 2; mi++)
        #pragma unroll
        for (int ni = 0; ni < 8; ni++)
            #pragma unroll
            for (int q = 0; q < 4; q++) c[mi][ni][q] = 0.f;

    auto gload = [&](int kt, int buf){
        const int k0 = kt * BK;
        #pragma unroll
        for (int p = 0; p < 4; p++){
            const int id = tid + p * 128;
            const int r = id >> 3, ck = (id & 7) * 8;
            cpa16(sbase + 2u * (buf * A_BUF + r * AST + ck),
                  Asrc + (size_t)(m0 + r) * DIM + k0 + ck);
        }
        #pragma unroll
        for (int p = 0; p < 8; p++){
            const int id = tid + p * 128;
            const int r = id >> 3, ck = (id & 7) * 8;
            cpa16(sbase + 2u * (2 * A_BUF + buf * B_BUF + r * AST + ck),
                  Wsrc + (size_t)(n0 + r) * DIM + k0 + ck);
        }
        asm volatile("cp.async.commit_group;\n");
    };

    const int lrow = (lane & 7) + ((lane >> 3) & 1) * 8;
    const int lksel = (lane & 16) ? 8 : 0;

    auto compute = [&](int buf){
        const uint32_t aoff = buf * A_BUF;
        const uint32_t boff = 2 * A_BUF + buf * B_BUF;
        #pragma unroll
        for (int ks = 0; ks < 4; ks++){
            const int kk = ks * 16 + lksel;
            uint32_t a[2][4], bb[4][4];
            #pragma unroll
            for (int mi = 0; mi < 2; mi++){
                const int row = wm + mi * 16 + lrow;
                ldsm4(a[mi][0], a[mi][1], a[mi][2], a[mi][3],
                      sbase + 2u * (aoff + row * AST + kk));
            }
            #pragma unroll
            for (int nip = 0; nip < 4; nip++){
                const int nrow = wn + nip * 16 + lrow;
                ldsm4(bb[nip][0], bb[nip][1], bb[nip][2], bb[nip][3],
                      sbase + 2u * (boff + nrow * AST + kk));
            }
            #pragma unroll
            for (int mi = 0; mi < 2; mi++)
                #pragma unroll
                for (int nip = 0; nip < 4; nip++){
                    mma_f16(c[mi][2 * nip    ], a[mi], bb[nip][0], bb[nip][2]);
                    mma_f16(c[mi][2 * nip + 1], a[mi], bb[nip][1], bb[nip][3]);
                }
        }
    };

    gload(0, 0);
    int buf = 0;
    #pragma unroll 1
    for (int kt = 0; kt < DIM / BK; ++kt){
        const bool more = (kt + 1 < DIM / BK);
        if (more) gload(kt + 1, buf ^ 1);
        if (more) { asm volatile("cp.async.wait_group 1;\n"); }
        else      { asm volatile("cp.async.wait_group 0;\n"); }
        __syncthreads();
        compute(buf);
        __syncthreads();
        buf ^= 1;
    }

    #pragma unroll
    for (int mi = 0; mi < 2; mi++){
        #pragma unroll
        for (int ni = 0; ni < 8; ni++){
            const int row = m0 + wm + mi * 16 + (lane >> 2);
            const int col = n0 + wn + ni * 8 + (lane & 3) * 2;
            if (MODE == 3){
                float2 bv = *reinterpret_cast<const float2*>(&bias[col]);
                float2 o0 = make_float2(c[mi][ni][0] + bv.x, c[mi][ni][1] + bv.y);
                float2 o1 = make_float2(c[mi][ni][2] + bv.x, c[mi][ni][3] + bv.y);
                *reinterpret_cast<float2*>(&outf[(size_t)row * DIM + col])       = o0;
                *reinterpret_cast<float2*>(&outf[(size_t)(row + 8) * DIM + col]) = o1;
            } else {
                __half* dst = (MODE == 0) ? g_Q : (MODE == 1) ? g_K : g_V;
                __half2 h0 = __floats2half2_rn(c[mi][ni][0], c[mi][ni][1]);
                __half2 h1 = __floats2half2_rn(c[mi][ni][2], c[mi][ni][3]);
                *reinterpret_cast<__half2*>(&dst[(size_t)row * DIM + col])       = h0;
                *reinterpret_cast<__half2*>(&dst[(size_t)(row + 8) * DIM + col]) = h1;
            }
        }
    }
}

// ---------------- MMA attention: one block per (head h, batch b) ----------------
#define KST 72    // K/V smem row stride (halves)
#define PST 136   // P smem row stride (halves)
__global__ __launch_bounds__(128, 5)
void attn_kernel()
{
    const int h = blockIdx.x;
    const int b = blockIdx.y;
    const int rowlim = b & (NLAT - 1);
    const int L  = rowlim + 1;
    const int Lk = ((rowlim >> 4) + 1) << 4;     // ceil(L/16)*16
    const int tid = threadIdx.x, lane = tid & 31, warp = tid >> 5;

    __shared__ __half Qs[NTOK * KST];
    __shared__ __half Ks[NLAT * KST];
    __shared__ __half Vs[NLAT * KST];
    __shared__ __half Ps[NTOK * PST];
    __shared__ float  Rinv[NTOK];

    // ---- loads (16B) ----
    {
        const int i = tid >> 3, c8 = (tid & 7) * 8;
        *reinterpret_cast<uint4*>(&Qs[i * KST + c8]) =
            *reinterpret_cast<const uint4*>(&g_Q[(size_t)(b * NTOK + i) * DIM + h * 64 + c8]);
    }
    for (int r0 = 0; r0 < Lk; r0 += 16){
        const int j = r0 + (tid >> 3), c8 = (tid & 7) * 8;
        const size_t g = (size_t)(b * NLAT + j) * DIM + h * 64 + c8;
        *reinterpret_cast<uint4*>(&Ks[j * KST + c8]) = *reinterpret_cast<const uint4*>(&g_K[g]);
        *reinterpret_cast<uint4*>(&Vs[j * KST + c8]) = *reinterpret_cast<const uint4*>(&g_V[g]);
    }
    __syncthreads();

    const uint32_t qb = (uint32_t)__cvta_generic_to_shared(Qs);
    const uint32_t kb = (uint32_t)__cvta_generic_to_shared(Ks);
    const uint32_t vb = (uint32_t)__cvta_generic_to_shared(Vs);
    const uint32_t pb = (uint32_t)__cvta_generic_to_shared(Ps);
    const int lrow  = (lane & 7) + ((lane >> 3) & 1) * 8;
    const int lksel = (lane & 16) ? 8 : 0;

    // ---- scores: S(16 x L) = Q(16x64) @ K^T, warp w -> latents [32w, 32w+32) ----
    if (warp * 32 <= rowlim){
        uint32_t a[4][4];
        #pragma unroll
        for (int ks = 0; ks < 4; ks++)
            ldsm4(a[ks][0], a[ks][1], a[ks][2], a[ks][3],
                  qb + 2u * (lrow * KST + ks * 16 + lksel));

        #pragma unroll
        for (int sub = 0; sub < 2; sub++){
            const int jb = warp * 32 + sub * 16;
            if (jb > rowlim) break;
            float c0[4] = {0,0,0,0}, c1[4] = {0,0,0,0};
            #pragma unroll
            for (int ks = 0; ks < 4; ks++){
                uint32_t bbq[4];
                ldsm4(bbq[0], bbq[1], bbq[2], bbq[3],
                      kb + 2u * ((jb + lrow) * KST + ks * 16 + lksel));
                mma_f16(c0, a[ks], bbq[0], bbq[2]);
                mma_f16(c1, a[ks], bbq[1], bbq[3]);
            }
            // epilogue: scale + mask(->0) + store fp16
            const int r  = lane >> 2;
            const int cc = (lane & 3) * 2;
            #pragma unroll
            for (int t = 0; t < 2; t++){
                const float* cs = t ? c1 : c0;
                const int j0 = jb + t * 8 + cc;
                const float v0 = (j0     <= rowlim) ? cs[0] * 0.125f : 0.f;
                const float v1 = (j0 + 1 <= rowlim) ? cs[1] * 0.125f : 0.f;
                const float v2 = (j0     <= rowlim) ? cs[2] * 0.125f : 0.f;
                const float v3 = (j0 + 1 <= rowlim) ? cs[3] * 0.125f : 0.f;
                *reinterpret_cast<__half2*>(&Ps[r * PST + j0])       = __floats2half2_rn(v0, v1);
                *reinterpret_cast<__half2*>(&Ps[(r + 8) * PST + j0]) = __floats2half2_rn(v2, v3);
            }
        }
    }
    __syncthreads();

    // ---- softmax per token row (warp per row), only cols < L ----
    for (int i = warp; i < NTOK; i += 4){
        float m = -1e30f;
        for (int jj = lane; jj < L; jj += 32) m = fmaxf(m, __half2float(Ps[i * PST + jj]));
        #pragma unroll
        for (int o = 16; o > 0; o >>= 1) m = fmaxf(m, __shfl_xor_sync(0xffffffffu, m, o));
        float sum = 0.f;
        for (int jj = lane; jj < L; jj += 32){
            const float e = __expf(__half2float(Ps[i * PST + jj]) - m);
            Ps[i * PST + jj] = __float2half(e);
            sum += e;
        }
        #pragma unroll
        for (int o = 16; o > 0; o >>= 1) sum += __shfl_xor_sync(0xffffffffu, sum, o);
        if (lane == 0) Rinv[i] = 1.f / sum;
    }
    __syncthreads();

    // ---- O(16x64) = P(16xLk) @ V(Lkx64), warp w -> dims [16w, 16w+16) ----
    const int ksmax = (rowlim >> 4) + 1;
    float o0[4] = {0,0,0,0}, o1[4] = {0,0,0,0};
    #pragma unroll 1
    for (int ks = 0; ks < ksmax; ks++){
        const int jb = ks * 16;
        uint32_t ap[4], bv[4];
        ldsm4 (ap[0], ap[1], ap[2], ap[3], pb + 2u * (lrow * PST + jb + lksel));
        ldsm4t(bv[0], bv[1], bv[2], bv[3], vb + 2u * ((jb + lrow) * KST + warp * 16 + lksel));
        mma_f16(o0, ap, bv[0], bv[1]);
        mma_f16(o1, ap, bv[2], bv[3]);
    }
    {
        const int r  = lane >> 2;
        const int cc = (lane & 3) * 2;
        const float ri0 = Rinv[r], ri1 = Rinv[r + 8];
        __half2* A2 = reinterpret_cast<__half2*>(g_A);
        #pragma unroll
        for (int t = 0; t < 2; t++){
            const float* os = t ? o1 : o0;
            const int d = h * 64 + warp * 16 + t * 8 + cc;
            A2[((size_t)(b * NTOK + r)     * DIM + d) >> 1] = __floats2half2_rn(os[0] * ri0, os[1] * ri0);
            A2[((size_t)(b * NTOK + r + 8) * DIM + d) >> 1] = __floats2half2_rn(os[2] * ri1, os[3] * ri1);
        }
    }
}

extern "C" void kernel_launch(void* const* d_in, const int* in_sizes, int n_in,
                              void* d_out, int out_size)
{
    (void)in_sizes; (void)n_in; (void)out_size;
    const float* x  = (const float*)d_in[0];
    const float* l  = (const float*)d_in[1];
    const float* Wq = (const float*)d_in[2];
    const float* Wk = (const float*)d_in[3];
    const float* Wv = (const float*)d_in[4];
    const float* Wo = (const float*)d_in[5];
    const float* bo = (const float*)d_in[6];
    float* out = (float*)d_out;

    static bool attr_done = false;
    if (!attr_done){
        cudaFuncSetAttribute(gemm512<0>, cudaFuncAttributeMaxDynamicSharedMemorySize, GEMM_SMEM_BYTES);
        cudaFuncSetAttribute(gemm512<1>, cudaFuncAttributeMaxDynamicSharedMemorySize, GEMM_SMEM_BYTES);
        cudaFuncSetAttribute(gemm512<2>, cudaFuncAttributeMaxDynamicSharedMemorySize, GEMM_SMEM_BYTES);
        cudaFuncSetAttribute(gemm512<3>, cudaFuncAttributeMaxDynamicSharedMemorySize, GEMM_SMEM_BYTES);
        attr_done = true;
    }

    const dim3 blk(128);
    // fp32 -> fp16 staging
    {
        const int n4x = M_Q  * DIM / 4;
        const int n4l = M_KV * DIM / 4;
        const int n4w = DIM * DIM / 4;
        f2h_kernel<<<(n4x + 255) / 256, 256>>>((const float4*)x, n4x, 0);
        f2h_kernel<<<(n4l + 255) / 256, 256>>>((const float4*)l, n4l, 1);
        f2h_kernel<<<(n4w + 255) / 256, 256>>>((const float4*)Wq, n4w, 2);
        f2h_kernel<<<(n4w + 255) / 256, 256>>>((const float4*)Wk, n4w, 3);
        f2h_kernel<<<(n4w + 255) / 256, 256>>>((const float4*)Wv, n4w, 4);
        f2h_kernel<<<(n4w + 255) / 256, 256>>>((const float4*)Wo, n4w, 5);
    }

    gemm512<0><<<dim3(DIM / BN, M_Q  / BM), blk, GEMM_SMEM_BYTES>>>(nullptr, nullptr);
    gemm512<1><<<dim3(DIM / BN, M_KV / BM), blk, GEMM_SMEM_BYTES>>>(nullptr, nullptr);
    gemm512<2><<<dim3(DIM / BN, M_KV / BM), blk, GEMM_SMEM_BYTES>>>(nullptr, nullptr);
    attn_kernel<<<dim3(NH, NBATCH), blk>>>();
    gemm512<3><<<dim3(DIM / BN, M_Q  / BM), blk, GEMM_SMEM_BYTES>>>(bo, out);
}

// round 9
// speedup vs baseline: 3.0188x; 1.2020x over previous
#include <cuda_runtime.h>
#include <cuda_fp16.h>
#include <cstdint>

#define DIM      512
#define NLAT     128
#define NTOK     16
#define NBATCH   1024
#define NH       8
#define M_KV     (NBATCH*NLAT)   // 131072
#define M_Q      (NBATCH*NTOK)   // 16384
#define DIMDIM   (DIM*DIM)

// fp16 scratch (device globals: allocation-free, zero-initialized)
__device__ __half g_Q  [(size_t)M_Q  * DIM];
__device__ __half g_K  [(size_t)M_KV * DIM];
__device__ __half g_V  [(size_t)M_KV * DIM];
__device__ __half g_A  [(size_t)M_Q  * DIM];
__device__ __half g_x16[(size_t)M_Q  * DIM];
__device__ __half g_l16[(size_t)M_KV * DIM];
__device__ __half g_W16[4 * DIMDIM];        // Wq, Wk, Wv, Wo

// ---------------- fp32 -> fp16 staging ----------------
__global__ __launch_bounds__(256)
void f2h_x(const float4* __restrict__ in)
{
    const int i = blockIdx.x * 256 + threadIdx.x;
    if (i >= M_Q * DIM / 4) return;
    __half2* out = reinterpret_cast<__half2*>(g_x16);
    const float4 v = in[i];
    out[2*i] = __floats2half2_rn(v.x, v.y);
    out[2*i+1] = __floats2half2_rn(v.z, v.w);
}

__global__ __launch_bounds__(256)
void f2h_l(const float4* __restrict__ in, int i0, int iend)
{
    const int i = blockIdx.x * 256 + threadIdx.x + i0;
    if (i >= iend) return;
    const int row = i >> 7;                             // 128 float4 per 512-row
    if ((row & 127) > ((row >> 7) & 127)) return;       // latent never attended
    __half2* out = reinterpret_cast<__half2*>(g_l16);
    const float4 v = in[i];
    out[2*i] = __floats2half2_rn(v.x, v.y);
    out[2*i+1] = __floats2half2_rn(v.z, v.w);
}

__global__ __launch_bounds__(256)
void f2h_w4(const float4* __restrict__ a, const float4* __restrict__ b,
            const float4* __restrict__ c, const float4* __restrict__ d)
{
    const int i = blockIdx.x * 256 + threadIdx.x;      // 0 .. 4*65536-1
    if (i >= 4 * (DIMDIM / 4)) return;
    const int w = i >> 16, r = i & 65535;
    const float4* src = (w == 0) ? a : (w == 1) ? b : (w == 2) ? c : d;
    const float4 v = src[r];
    __half2* out = reinterpret_cast<__half2*>(g_W16) + (size_t)w * (DIMDIM / 2);
    out[2*r] = __floats2half2_rn(v.x, v.y);
    out[2*r+1] = __floats2half2_rn(v.z, v.w);
}

// ---------------- mma helpers ----------------
__device__ __forceinline__ void cpa16(uint32_t s, const void* g){
    asm volatile("cp.async.cg.shared.global [%0], [%1], 16;\n" :: "r"(s), "l"(g));
}
__device__ __forceinline__ void ldsm4(uint32_t& r0, uint32_t& r1, uint32_t& r2, uint32_t& r3,
                                      uint32_t addr){
    asm volatile("ldmatrix.sync.aligned.m8n8.x4.shared.b16 {%0,%1,%2,%3}, [%4];\n"
                 : "=r"(r0), "=r"(r1), "=r"(r2), "=r"(r3) : "r"(addr));
}
__device__ __forceinline__ void ldsm4t(uint32_t& r0, uint32_t& r1, uint32_t& r2, uint32_t& r3,
                                       uint32_t addr){
    asm volatile("ldmatrix.sync.aligned.m8n8.x4.trans.shared.b16 {%0,%1,%2,%3}, [%4];\n"
                 : "=r"(r0), "=r"(r1), "=r"(r2), "=r"(r3) : "r"(addr));
}
__device__ __forceinline__ void mma_f16(float c[4], const uint32_t a[4],
                                        uint32_t b0, uint32_t b1){
    asm volatile(
        "mma.sync.aligned.m16n8k16.row.col.f32.f16.f16.f32 "
        "{%0,%1,%2,%3}, {%4,%5,%6,%7}, {%8,%9}, {%0,%1,%2,%3};\n"
        : "+f"(c[0]), "+f"(c[1]), "+f"(c[2]), "+f"(c[3])
        : "r"(a[0]), "r"(a[1]), "r"(a[2]), "r"(a[3]), "r"(b0), "r"(b1));
}

// ---------------- Q / O projection GEMM (round-6 proven) ----------------
#define BM 64
#define BN 128
#define BK 64
#define AST   72
#define A_BUF (BM * AST)
#define B_BUF (BN * AST)
#define GEMM_SMEM_BYTES ((2 * A_BUF + 2 * B_BUF) * 2)   // 55296 B

template<int MODE>   // 0: Q proj (x16 -> g_Q), 3: out proj (g_A -> fp32 out + bias)
__global__ __launch_bounds__(128, 4)
void gemm512(const float* __restrict__ bias, float* __restrict__ outf)
{
    const int m0 = blockIdx.y * BM;
    const int n0 = blockIdx.x * BN;

    const __half* __restrict__ Asrc = (MODE == 0) ? g_x16 : g_A;
    const __half* __restrict__ Wsrc = g_W16 + (size_t)MODE * DIMDIM;

    extern __shared__ __half sh[];
    const uint32_t sbase = (uint32_t)__cvta_generic_to_shared(sh);

    const int tid  = threadIdx.x;
    const int lane = tid & 31;
    const int warp = tid >> 5;
    const int wm   = (warp >> 1) * 32;
    const int wn   = (warp & 1)  * 64;

    float c[2][8][4];
    #pragma unroll
    for (int mi = 0; mi < 2; mi++)
        #pragma unroll
        for (int ni = 0; ni < 8; ni++)
            #pragma unroll
            for (int q = 0; q < 4; q++) c[mi][ni][q] = 0.f;

    auto gload = [&](int kt, int buf){
        const int k0 = kt * BK;
        #pragma unroll
        for (int p = 0; p < 4; p++){
            const int id = tid + p * 128;
            const int r = id >> 3, ck = (id & 7) * 8;
            cpa16(sbase + 2u * (buf * A_BUF + r * AST + ck),
                  Asrc + (size_t)(m0 + r) * DIM + k0 + ck);
        }
        #pragma unroll
        for (int p = 0; p < 8; p++){
            const int id = tid + p * 128;
            const int r = id >> 3, ck = (id & 7) * 8;
            cpa16(sbase + 2u * (2 * A_BUF + buf * B_BUF + r * AST + ck),
                  Wsrc + (size_t)(n0 + r) * DIM + k0 + ck);
        }
        asm volatile("cp.async.commit_group;\n");
    };

    const int lrow = (lane & 7) + ((lane >> 3) & 1) * 8;
    const int lksel = (lane & 16) ? 8 : 0;

    auto compute = [&](int buf){
        const uint32_t aoff = buf * A_BUF;
        const uint32_t boff = 2 * A_BUF + buf * B_BUF;
        #pragma unroll
        for (int ks = 0; ks < 4; ks++){
            const int kk = ks * 16 + lksel;
            uint32_t a[2][4], bb[4][4];
            #pragma unroll
            for (int mi = 0; mi < 2; mi++){
                const int row = wm + mi * 16 + lrow;
                ldsm4(a[mi][0], a[mi][1], a[mi][2], a[mi][3],
                      sbase + 2u * (aoff + row * AST + kk));
            }
            #pragma unroll
            for (int nip = 0; nip < 4; nip++){
                const int nrow = wn + nip * 16 + lrow;
                ldsm4(bb[nip][0], bb[nip][1], bb[nip][2], bb[nip][3],
                      sbase + 2u * (boff + nrow * AST + kk));
            }
            #pragma unroll
            for (int mi = 0; mi < 2; mi++)
                #pragma unroll
                for (int nip = 0; nip < 4; nip++){
                    mma_f16(c[mi][2 * nip    ], a[mi], bb[nip][0], bb[nip][2]);
                    mma_f16(c[mi][2 * nip + 1], a[mi], bb[nip][1], bb[nip][3]);
                }
        }
    };

    gload(0, 0);
    int buf = 0;
    #pragma unroll 1
    for (int kt = 0; kt < DIM / BK; ++kt){
        const bool more = (kt + 1 < DIM / BK);
        if (more) gload(kt + 1, buf ^ 1);
        if (more) { asm volatile("cp.async.wait_group 1;\n"); }
        else      { asm volatile("cp.async.wait_group 0;\n"); }
        __syncthreads();
        compute(buf);
        __syncthreads();
        buf ^= 1;
    }

    #pragma unroll
    for (int mi = 0; mi < 2; mi++){
        #pragma unroll
        for (int ni = 0; ni < 8; ni++){
            const int row = m0 + wm + mi * 16 + (lane >> 2);
            const int col = n0 + wn + ni * 8 + (lane & 3) * 2;
            if (MODE == 3){
                float2 bv = *reinterpret_cast<const float2*>(&bias[col]);
                float2 o0 = make_float2(c[mi][ni][0] + bv.x, c[mi][ni][1] + bv.y);
                float2 o1 = make_float2(c[mi][ni][2] + bv.x, c[mi][ni][3] + bv.y);
                *reinterpret_cast<float2*>(&outf[(size_t)row * DIM + col])       = o0;
                *reinterpret_cast<float2*>(&outf[(size_t)(row + 8) * DIM + col]) = o1;
            } else {
                __half2 h0 = __floats2half2_rn(c[mi][ni][0], c[mi][ni][1]);
                __half2 h1 = __floats2half2_rn(c[mi][ni][2], c[mi][ni][3]);
                *reinterpret_cast<__half2*>(&g_Q[(size_t)row * DIM + col])       = h0;
                *reinterpret_cast<__half2*>(&g_Q[(size_t)(row + 8) * DIM + col]) = h1;
            }
        }
    }
}

// ---------------- fused K+V projection with dense row remap ----------------
// Valid K/V rows: (batch b, latent j) with j <= b&127. Within each 128-batch group,
// pair batch rowlim r with rowlim 126-r -> (r+1)+(127-r)=128 rows = one dense tile.
// 65 tiles/group (t=0..62 pairs, t=63 half [batch r=63], t=64 full [r=127]).
__device__ __forceinline__ void maprow(int g, int t, int i, int& grow, bool& val){
    int bsel, j; val = true;
    if (t == 64){ bsel = 127; j = i; }
    else if (t == 63){ bsel = 63; j = i; val = (i < 64); }
    else if (i <= t){ bsel = t; j = i; }
    else { bsel = 126 - t; j = i - t - 1; }
    grow = ((g << 7) + bsel) * NLAT + j;
}

#define KAST  72
#define KA_CH (128 * KAST)               // 9216 halves per stage tile
#define KSTG  (3 * KA_CH)                // A + BK + BV per stage
#define KV_SMEM_BYTES (3 * KSTG * 2)     // 3 stages = 165888 B

__global__ __launch_bounds__(256, 1)
void gemm_kv()
{
    const int n0 = blockIdx.x * 128;
    const int my = blockIdx.y;
    const int g = my / 65;
    const int t = my - g * 65;

    extern __shared__ __half sh[];
    const uint32_t sb = (uint32_t)__cvta_generic_to_shared(sh);

    const int tid = threadIdx.x, lane = tid & 31, warp = tid >> 5;
    const int wm = (warp >> 1) * 32;   // 0/32/64/96
    const int wn = (warp & 1) * 64;    // 0/64

    // per-thread global row bases (4 rows each, stride 32)
    const int ck = (tid & 7) * 8;
    const int rbase = tid >> 3;        // 0..31
    const __half* abase[4]; bool aval[4];
    const __half* kbase[4];
    #pragma unroll
    for (int p = 0; p < 4; p++){
        int grow; bool v;
        maprow(g, t, rbase + 32 * p, grow, v);
        abase[p] = g_l16 + (size_t)grow * DIM + ck;
        aval[p] = v;
        kbase[p] = g_W16 + (size_t)DIMDIM + (size_t)(n0 + rbase + 32 * p) * DIM + ck;
    }

    float cK[2][8][4], cV[2][8][4];
    #pragma unroll
    for (int mi = 0; mi < 2; mi++)
        #pragma unroll
        for (int ni = 0; ni < 8; ni++)
            #pragma unroll
            for (int q = 0; q < 4; q++){ cK[mi][ni][q] = 0.f; cV[mi][ni][q] = 0.f; }

    auto load = [&](int c, int s){
        const int k0 = c * 64;
        const uint32_t so = (uint32_t)s * KSTG;
        #pragma unroll
        for (int p = 0; p < 4; p++){
            const int r = rbase + 32 * p;
            if (aval[p])
                cpa16(sb + 2u * (so + r * KAST + ck), abase[p] + k0);
            cpa16(sb + 2u * (so + KA_CH + r * KAST + ck), kbase[p] + k0);
            cpa16(sb + 2u * (so + 2 * KA_CH + r * KAST + ck), kbase[p] + DIMDIM + k0);
        }
        asm volatile("cp.async.commit_group;\n");
    };

    const int lrow = (lane & 7) + ((lane >> 3) & 1) * 8;
    const int lksel = (lane & 16) ? 8 : 0;

    auto compute = [&](int s){
        const uint32_t ao = (uint32_t)s * KSTG;
        #pragma unroll
        for (int ks = 0; ks < 4; ks++){
            const int kk = ks * 16 + lksel;
            uint32_t a[2][4];
            #pragma unroll
            for (int mi = 0; mi < 2; mi++)
                ldsm4(a[mi][0], a[mi][1], a[mi][2], a[mi][3],
                      sb + 2u * (ao + (wm + mi * 16 + lrow) * KAST + kk));
            uint32_t bq[4][4];
            #pragma unroll
            for (int nip = 0; nip < 4; nip++)
                ldsm4(bq[nip][0], bq[nip][1], bq[nip][2], bq[nip][3],
                      sb + 2u * (ao + KA_CH + (wn + nip * 16 + lrow) * KAST + kk));
            #pragma unroll
            for (int mi = 0; mi < 2; mi++)
                #pragma unroll
                for (int nip = 0; nip < 4; nip++){
                    mma_f16(cK[mi][2 * nip    ], a[mi], bq[nip][0], bq[nip][2]);
                    mma_f16(cK[mi][2 * nip + 1], a[mi], bq[nip][1], bq[nip][3]);
                }
            #pragma unroll
            for (int nip = 0; nip < 4; nip++)
                ldsm4(bq[nip][0], bq[nip][1], bq[nip][2], bq[nip][3],
                      sb + 2u * (ao + 2 * KA_CH + (wn + nip * 16 + lrow) * KAST + kk));
            #pragma unroll
            for (int mi = 0; mi < 2; mi++)
                #pragma unroll
                for (int nip = 0; nip < 4; nip++){
                    mma_f16(cV[mi][2 * nip    ], a[mi], bq[nip][0], bq[nip][2]);
                    mma_f16(cV[mi][2 * nip + 1], a[mi], bq[nip][1], bq[nip][3]);
                }
        }
    };

    load(0, 0); load(1, 1);
    #pragma unroll 1
    for (int c = 0; c < 8; c++){
        if (c < 7) { asm volatile("cp.async.wait_group 1;\n"); }
        else       { asm volatile("cp.async.wait_group 0;\n"); }
        __syncthreads();
        compute(c % 3);
        if (c < 6) load(c + 2, (c + 2) % 3);
    }

    // epilogue: map tile rows back to (batch, latent) rows, masked stores
    int grows[4]; bool vals[4];
    const int r4 = lane >> 2;
    #pragma unroll
    for (int q = 0; q < 4; q++)
        maprow(g, t, wm + q * 8 + r4, grows[q], vals[q]);

    #pragma unroll
    for (int mi = 0; mi < 2; mi++){
        #pragma unroll
        for (int ni = 0; ni < 8; ni++){
            const int col = n0 + wn + ni * 8 + (lane & 3) * 2;
            const int q0 = mi * 2, q1 = mi * 2 + 1;
            if (vals[q0]){
                *reinterpret_cast<__half2*>(&g_K[(size_t)grows[q0] * DIM + col]) =
                    __floats2half2_rn(cK[mi][ni][0], cK[mi][ni][1]);
                *reinterpret_cast<__half2*>(&g_V[(size_t)grows[q0] * DIM + col]) =
                    __floats2half2_rn(cV[mi][ni][0], cV[mi][ni][1]);
            }
            if (vals[q1]){
                *reinterpret_cast<__half2*>(&g_K[(size_t)grows[q1] * DIM + col]) =
                    __floats2half2_rn(cK[mi][ni][2], cK[mi][ni][3]);
                *reinterpret_cast<__half2*>(&g_V[(size_t)grows[q1] * DIM + col]) =
                    __floats2half2_rn(cV[mi][ni][2], cV[mi][ni][3]);
            }
        }
    }
}

// ---------------- MMA attention (round-8 proven) ----------------
#define KST 72
#define PST 136
__global__ __launch_bounds__(128, 5)
void attn_kernel()
{
    const int h = blockIdx.x;
    const int b = blockIdx.y;
    const int rowlim = b & (NLAT - 1);
    const int L  = rowlim + 1;
    const int Lk = ((rowlim >> 4) + 1) << 4;
    const int tid = threadIdx.x, lane = tid & 31, warp = tid >> 5;

    __shared__ __half Qs[NTOK * KST];
    __shared__ __half Ks[NLAT * KST];
    __shared__ __half Vs[NLAT * KST];
    __shared__ __half Ps[NTOK * PST];
    __shared__ float  Rinv[NTOK];

    {
        const int i = tid >> 3, c8 = (tid & 7) * 8;
        *reinterpret_cast<uint4*>(&Qs[i * KST + c8]) =
            *reinterpret_cast<const uint4*>(&g_Q[(size_t)(b * NTOK + i) * DIM + h * 64 + c8]);
    }
    for (int r0 = 0; r0 < Lk; r0 += 16){
        const int j = r0 + (tid >> 3), c8 = (tid & 7) * 8;
        const size_t g = (size_t)(b * NLAT + j) * DIM + h * 64 + c8;
        *reinterpret_cast<uint4*>(&Ks[j * KST + c8]) = *reinterpret_cast<const uint4*>(&g_K[g]);
        *reinterpret_cast<uint4*>(&Vs[j * KST + c8]) = *reinterpret_cast<const uint4*>(&g_V[g]);
    }
    __syncthreads();

    const uint32_t qb = (uint32_t)__cvta_generic_to_shared(Qs);
    const uint32_t kb = (uint32_t)__cvta_generic_to_shared(Ks);
    const uint32_t vb = (uint32_t)__cvta_generic_to_shared(Vs);
    const uint32_t pb = (uint32_t)__cvta_generic_to_shared(Ps);
    const int lrow  = (lane & 7) + ((lane >> 3) & 1) * 8;
    const int lksel = (lane & 16) ? 8 : 0;

    if (warp * 32 <= rowlim){
        uint32_t a[4][4];
        #pragma unroll
        for (int ks = 0; ks < 4; ks++)
            ldsm4(a[ks][0], a[ks][1], a[ks][2], a[ks][3],
                  qb + 2u * (lrow * KST + ks * 16 + lksel));

        #pragma unroll
        for (int sub = 0; sub < 2; sub++){
            const int jb = warp * 32 + sub * 16;
            if (jb > rowlim) break;
            float c0[4] = {0,0,0,0}, c1[4] = {0,0,0,0};
            #pragma unroll
            for (int ks = 0; ks < 4; ks++){
                uint32_t bbq[4];
                ldsm4(bbq[0], bbq[1], bbq[2], bbq[3],
                      kb + 2u * ((jb + lrow) * KST + ks * 16 + lksel));
                mma_f16(c0, a[ks], bbq[0], bbq[2]);
                mma_f16(c1, a[ks], bbq[1], bbq[3]);
            }
            const int r  = lane >> 2;
            const int cc = (lane & 3) * 2;
            #pragma unroll
            for (int t = 0; t < 2; t++){
                const float* cs = t ? c1 : c0;
                const int j0 = jb + t * 8 + cc;
                const float v0 = (j0     <= rowlim) ? cs[0] * 0.125f : 0.f;
                const float v1 = (j0 + 1 <= rowlim) ? cs[1] * 0.125f : 0.f;
                const float v2 = (j0     <= rowlim) ? cs[2] * 0.125f : 0.f;
                const float v3 = (j0 + 1 <= rowlim) ? cs[3] * 0.125f : 0.f;
                *reinterpret_cast<__half2*>(&Ps[r * PST + j0])       = __floats2half2_rn(v0, v1);
                *reinterpret_cast<__half2*>(&Ps[(r + 8) * PST + j0]) = __floats2half2_rn(v2, v3);
            }
        }
    }
    __syncthreads();

    for (int i = warp; i < NTOK; i += 4){
        float m = -1e30f;
        for (int jj = lane; jj < L; jj += 32) m = fmaxf(m, __half2float(Ps[i * PST + jj]));
        #pragma unroll
        for (int o = 16; o > 0; o >>= 1) m = fmaxf(m, __shfl_xor_sync(0xffffffffu, m, o));
        float sum = 0.f;
        for (int jj = lane; jj < L; jj += 32){
            const float e = __expf(__half2float(Ps[i * PST + jj]) - m);
            Ps[i * PST + jj] = __float2half(e);
            sum += e;
        }
        #pragma unroll
        for (int o = 16; o > 0; o >>= 1) sum += __shfl_xor_sync(0xffffffffu, sum, o);
        if (lane == 0) Rinv[i] = 1.f / sum;
    }
    __syncthreads();

    const int ksmax = (rowlim >> 4) + 1;
    float o0[4] = {0,0,0,0}, o1[4] = {0,0,0,0};
    #pragma unroll 1
    for (int ks = 0; ks < ksmax; ks++){
        const int jb = ks * 16;
        uint32_t ap[4], bv[4];
        ldsm4 (ap[0], ap[1], ap[2], ap[3], pb + 2u * (lrow * PST + jb + lksel));
        ldsm4t(bv[0], bv[1], bv[2], bv[3], vb + 2u * ((jb + lrow) * KST + warp * 16 + lksel));
        mma_f16(o0, ap, bv[0], bv[1]);
        mma_f16(o1, ap, bv[2], bv[3]);
    }
    {
        const int r  = lane >> 2;
        const int cc = (lane & 3) * 2;
        const float ri0 = Rinv[r], ri1 = Rinv[r + 8];
        __half2* A2 = reinterpret_cast<__half2*>(g_A);
        #pragma unroll
        for (int t = 0; t < 2; t++){
            const float* os = t ? o1 : o0;
            const int d = h * 64 + warp * 16 + t * 8 + cc;
            A2[((size_t)(b * NTOK + r)     * DIM + d) >> 1] = __floats2half2_rn(os[0] * ri0, os[1] * ri0);
            A2[((size_t)(b * NTOK + r + 8) * DIM + d) >> 1] = __floats2half2_rn(os[2] * ri1, os[3] * ri1);
        }
    }
}

extern "C" void kernel_launch(void* const* d_in, const int* in_sizes, int n_in,
                              void* d_out, int out_size)
{
    (void)in_sizes; (void)n_in; (void)out_size;
    const float* x  = (const float*)d_in[0];
    const float* l  = (const float*)d_in[1];
    const float* Wq = (const float*)d_in[2];
    const float* Wk = (const float*)d_in[3];
    const float* Wv = (const float*)d_in[4];
    const float* Wo = (const float*)d_in[5];
    const float* bo = (const float*)d_in[6];
    float* out = (float*)d_out;

    static bool attr_done = false;
    if (!attr_done){
        cudaFuncSetAttribute(gemm512<0>, cudaFuncAttributeMaxDynamicSharedMemorySize, GEMM_SMEM_BYTES);
        cudaFuncSetAttribute(gemm512<3>, cudaFuncAttributeMaxDynamicSharedMemorySize, GEMM_SMEM_BYTES);
        cudaFuncSetAttribute(gemm_kv,   cudaFuncAttributeMaxDynamicSharedMemorySize, KV_SMEM_BYTES);
        attr_done = true;
    }

    const int n4x = M_Q  * DIM / 4;
    const int n4l = M_KV * DIM / 4;
    const int n4l_half = n4l / 2;

    // launches 1..4: staging (ordered so launch #6 = gemm_kv for ncu -s 5 -c 1)
    f2h_x <<<(n4x + 255) / 256, 256>>>((const float4*)x);
    f2h_w4<<<(4 * DIMDIM / 4 + 255) / 256, 256>>>((const float4*)Wq, (const float4*)Wk,
                                                  (const float4*)Wv, (const float4*)Wo);
    f2h_l <<<(n4l_half + 255) / 256, 256>>>((const float4*)l, 0, n4l_half);
    f2h_l <<<(n4l_half + 255) / 256, 256>>>((const float4*)l, n4l_half, n4l);

    // launch 5: Q projection
    gemm512<0><<<dim3(DIM / BN, M_Q / BM), 128, GEMM_SMEM_BYTES>>>(nullptr, nullptr);
    // launch 6: fused K+V projection (dense remapped tiles)
    gemm_kv<<<dim3(4, 520), 256, KV_SMEM_BYTES>>>();
    // launch 7: attention
    attn_kernel<<<dim3(NH, NBATCH), 128>>>();
    // launch 8: out projection
    gemm512<3><<<dim3(DIM / BN, M_Q / BM), 128, GEMM_SMEM_BYTES>>>(bo, out);
}

// round 10
// speedup vs baseline: 3.2242x; 1.0680x over previous
#include <cuda_runtime.h>
#include <cuda_fp16.h>
#include <cstdint>

#define DIM      512
#define NLAT     128
#define NTOK     16
#define NBATCH   1024
#define NH       8
#define M_KV     (NBATCH*NLAT)   // 131072
#define M_Q      (NBATCH*NTOK)   // 16384
#define DIMDIM   (DIM*DIM)

// fp16 scratch (device globals: allocation-free, zero-initialized)
__device__ __half g_Q  [(size_t)M_Q  * DIM];
__device__ __half g_K  [(size_t)M_KV * DIM];
__device__ __half g_V  [(size_t)M_KV * DIM];
__device__ __half g_A  [(size_t)M_Q  * DIM];
__device__ __half g_x16[(size_t)M_Q  * DIM];
__device__ __half g_l16[(size_t)M_KV * DIM];
__device__ __half g_W16[4 * DIMDIM];        // Wq, Wk, Wv, Wo

// ---------------- fp32 -> fp16 staging ----------------
__global__ __launch_bounds__(256)
void f2h_x(const float4* __restrict__ in)
{
    const int i = blockIdx.x * 256 + threadIdx.x;
    if (i >= M_Q * DIM / 4) return;
    __half2* out = reinterpret_cast<__half2*>(g_x16);
    const float4 v = in[i];
    out[2*i] = __floats2half2_rn(v.x, v.y);
    out[2*i+1] = __floats2half2_rn(v.z, v.w);
}

__global__ __launch_bounds__(256)
void f2h_l(const float4* __restrict__ in, int i0, int iend)
{
    const int i = blockIdx.x * 256 + threadIdx.x + i0;
    if (i >= iend) return;
    const int row = i >> 7;                             // 128 float4 per 512-row
    if ((row & 127) > ((row >> 7) & 127)) return;       // latent never attended
    __half2* out = reinterpret_cast<__half2*>(g_l16);
    const float4 v = in[i];
    out[2*i] = __floats2half2_rn(v.x, v.y);
    out[2*i+1] = __floats2half2_rn(v.z, v.w);
}

__global__ __launch_bounds__(256)
void f2h_w4(const float4* __restrict__ a, const float4* __restrict__ b,
            const float4* __restrict__ c, const float4* __restrict__ d)
{
    const int i = blockIdx.x * 256 + threadIdx.x;      // 0 .. 4*65536-1
    if (i >= 4 * (DIMDIM / 4)) return;
    const int w = i >> 16, r = i & 65535;
    const float4* src = (w == 0) ? a : (w == 1) ? b : (w == 2) ? c : d;
    const float4 v = src[r];
    __half2* out = reinterpret_cast<__half2*>(g_W16) + (size_t)w * (DIMDIM / 2);
    out[2*r] = __floats2half2_rn(v.x, v.y);
    out[2*r+1] = __floats2half2_rn(v.z, v.w);
}

// ---------------- mma helpers ----------------
__device__ __forceinline__ void cpa16(uint32_t s, const void* g){
    asm volatile("cp.async.cg.shared.global [%0], [%1], 16;\n" :: "r"(s), "l"(g));
}
__device__ __forceinline__ void ldsm4(uint32_t& r0, uint32_t& r1, uint32_t& r2, uint32_t& r3,
                                      uint32_t addr){
    asm volatile("ldmatrix.sync.aligned.m8n8.x4.shared.b16 {%0,%1,%2,%3}, [%4];\n"
                 : "=r"(r0), "=r"(r1), "=r"(r2), "=r"(r3) : "r"(addr));
}
__device__ __forceinline__ void ldsm4t(uint32_t& r0, uint32_t& r1, uint32_t& r2, uint32_t& r3,
                                       uint32_t addr){
    asm volatile("ldmatrix.sync.aligned.m8n8.x4.trans.shared.b16 {%0,%1,%2,%3}, [%4];\n"
                 : "=r"(r0), "=r"(r1), "=r"(r2), "=r"(r3) : "r"(addr));
}
__device__ __forceinline__ void mma_f16(float c[4], const uint32_t a[4],
                                        uint32_t b0, uint32_t b1){
    asm volatile(
        "mma.sync.aligned.m16n8k16.row.col.f32.f16.f16.f32 "
        "{%0,%1,%2,%3}, {%4,%5,%6,%7}, {%8,%9}, {%0,%1,%2,%3};\n"
        : "+f"(c[0]), "+f"(c[1]), "+f"(c[2]), "+f"(c[3])
        : "r"(a[0]), "r"(a[1]), "r"(a[2]), "r"(a[3]), "r"(b0), "r"(b1));
}

// ---------------- Q / O projection GEMM ----------------
#define BM 64
#define BN 128
#define BK 64
#define AST   72
#define A_BUF (BM * AST)
#define B_BUF (BN * AST)
#define GEMM_SMEM_BYTES ((2 * A_BUF + 2 * B_BUF) * 2)   // 55296 B

template<int MODE>   // 0: Q proj (x16 -> g_Q), 3: out proj (g_A -> fp32 out + bias)
__global__ __launch_bounds__(128, 4)
void gemm512(const float* __restrict__ bias, float* __restrict__ outf, int y0)
{
    const int m0 = (blockIdx.y + y0) * BM;
    const int n0 = blockIdx.x * BN;

    const __half* __restrict__ Asrc = (MODE == 0) ? g_x16 : g_A;
    const __half* __restrict__ Wsrc = g_W16 + (size_t)MODE * DIMDIM;

    extern __shared__ __half sh[];
    const uint32_t sbase = (uint32_t)__cvta_generic_to_shared(sh);

    const int tid  = threadIdx.x;
    const int lane = tid & 31;
    const int warp = tid >> 5;
    const int wm   = (warp >> 1) * 32;
    const int wn   = (warp & 1)  * 64;

    float c[2][8][4];
    #pragma unroll
    for (int mi = 0; mi < 2; mi++)
        #pragma unroll
        for (int ni = 0; ni < 8; ni++)
            #pragma unroll
            for (int q = 0; q < 4; q++) c[mi][ni][q] = 0.f;

    auto gload = [&](int kt, int buf){
        const int k0 = kt * BK;
        #pragma unroll
        for (int p = 0; p < 4; p++){
            const int id = tid + p * 128;
            const int r = id >> 3, ck = (id & 7) * 8;
            cpa16(sbase + 2u * (buf * A_BUF + r * AST + ck),
                  Asrc + (size_t)(m0 + r) * DIM + k0 + ck);
        }
        #pragma unroll
        for (int p = 0; p < 8; p++){
            const int id = tid + p * 128;
            const int r = id >> 3, ck = (id & 7) * 8;
            cpa16(sbase + 2u * (2 * A_BUF + buf * B_BUF + r * AST + ck),
                  Wsrc + (size_t)(n0 + r) * DIM + k0 + ck);
        }
        asm volatile("cp.async.commit_group;\n");
    };

    const int lrow = (lane & 7) + ((lane >> 3) & 1) * 8;
    const int lksel = (lane & 16) ? 8 : 0;

    auto compute = [&](int buf){
        const uint32_t aoff = buf * A_BUF;
        const uint32_t boff = 2 * A_BUF + buf * B_BUF;
        #pragma unroll
        for (int ks = 0; ks < 4; ks++){
            const int kk = ks * 16 + lksel;
            uint32_t a[2][4], bb[4][4];
            #pragma unroll
            for (int mi = 0; mi < 2; mi++){
                const int row = wm + mi * 16 + lrow;
                ldsm4(a[mi][0], a[mi][1], a[mi][2], a[mi][3],
                      sbase + 2u * (aoff + row * AST + kk));
            }
            #pragma unroll
            for (int nip = 0; nip < 4; nip++){
                const int nrow = wn + nip * 16 + lrow;
                ldsm4(bb[nip][0], bb[nip][1], bb[nip][2], bb[nip][3],
                      sbase + 2u * (boff + nrow * AST + kk));
            }
            #pragma unroll
            for (int mi = 0; mi < 2; mi++)
                #pragma unroll
                for (int nip = 0; nip < 4; nip++){
                    mma_f16(c[mi][2 * nip    ], a[mi], bb[nip][0], bb[nip][2]);
                    mma_f16(c[mi][2 * nip + 1], a[mi], bb[nip][1], bb[nip][3]);
                }
        }
    };

    gload(0, 0);
    int buf = 0;
    #pragma unroll 1
    for (int kt = 0; kt < DIM / BK; ++kt){
        const bool more = (kt + 1 < DIM / BK);
        if (more) gload(kt + 1, buf ^ 1);
        if (more) { asm volatile("cp.async.wait_group 1;\n"); }
        else      { asm volatile("cp.async.wait_group 0;\n"); }
        __syncthreads();
        compute(buf);
        __syncthreads();
        buf ^= 1;
    }

    #pragma unroll
    for (int mi = 0; mi < 2; mi++){
        #pragma unroll
        for (int ni = 0; ni < 8; ni++){
            const int row = m0 + wm + mi * 16 + (lane >> 2);
            const int col = n0 + wn + ni * 8 + (lane & 3) * 2;
            if (MODE == 3){
                float2 bv = *reinterpret_cast<const float2*>(&bias[col]);
                float2 o0 = make_float2(c[mi][ni][0] + bv.x, c[mi][ni][1] + bv.y);
                float2 o1 = make_float2(c[mi][ni][2] + bv.x, c[mi][ni][3] + bv.y);
                *reinterpret_cast<float2*>(&outf[(size_t)row * DIM + col])       = o0;
                *reinterpret_cast<float2*>(&outf[(size_t)(row + 8) * DIM + col]) = o1;
            } else {
                __half2 h0 = __floats2half2_rn(c[mi][ni][0], c[mi][ni][1]);
                __half2 h1 = __floats2half2_rn(c[mi][ni][2], c[mi][ni][3]);
                *reinterpret_cast<__half2*>(&g_Q[(size_t)row * DIM + col])       = h0;
                *reinterpret_cast<__half2*>(&g_Q[(size_t)(row + 8) * DIM + col]) = h1;
            }
        }
    }
}

// ---------------- fused K+V projection with dense row remap ----------------
__device__ __forceinline__ void maprow(int g, int t, int i, int& grow, bool& val){
    int bsel, j; val = true;
    if (t == 64){ bsel = 127; j = i; }
    else if (t == 63){ bsel = 63; j = i; val = (i < 64); }
    else if (i <= t){ bsel = t; j = i; }
    else { bsel = 126 - t; j = i - t - 1; }
    grow = ((g << 7) + bsel) * NLAT + j;
}

#define KAST  72
#define KA_CH (128 * KAST)
#define KSTG  (3 * KA_CH)
#define KV_SMEM_BYTES (3 * KSTG * 2)     // 165888 B

__global__ __launch_bounds__(256, 1)
void gemm_kv(int y0)
{
    const int n0 = blockIdx.x * 128;
    const int my = blockIdx.y + y0;
    const int g = my / 65;
    const int t = my - g * 65;

    extern __shared__ __half sh[];
    const uint32_t sb = (uint32_t)__cvta_generic_to_shared(sh);

    const int tid = threadIdx.x, lane = tid & 31, warp = tid >> 5;
    const int wm = (warp >> 1) * 32;
    const int wn = (warp & 1) * 64;

    const int ck = (tid & 7) * 8;
    const int rbase = tid >> 3;
    const __half* abase[4]; bool aval[4];
    const __half* kbase[4];
    #pragma unroll
    for (int p = 0; p < 4; p++){
        int grow; bool v;
        maprow(g, t, rbase + 32 * p, grow, v);
        abase[p] = g_l16 + (size_t)grow * DIM + ck;
        aval[p] = v;
        kbase[p] = g_W16 + (size_t)DIMDIM + (size_t)(n0 + rbase + 32 * p) * DIM + ck;
    }

    float cK[2][8][4], cV[2][8][4];
    #pragma unroll
    for (int mi = 0; mi < 2; mi++)
        #pragma unroll
        for (int ni = 0; ni < 8; ni++)
            #pragma unroll
            for (int q = 0; q < 4; q++){ cK[mi][ni][q] = 0.f; cV[mi][ni][q] = 0.f; }

    auto load = [&](int c, int s){
        const int k0 = c * 64;
        const uint32_t so = (uint32_t)s * KSTG;
        #pragma unroll
        for (int p = 0; p < 4; p++){
            const int r = rbase + 32 * p;
            if (aval[p])
                cpa16(sb + 2u * (so + r * KAST + ck), abase[p] + k0);
            cpa16(sb + 2u * (so + KA_CH + r * KAST + ck), kbase[p] + k0);
            cpa16(sb + 2u * (so + 2 * KA_CH + r * KAST + ck), kbase[p] + DIMDIM + k0);
        }
        asm volatile("cp.async.commit_group;\n");
    };

    const int lrow = (lane & 7) + ((lane >> 3) & 1) * 8;
    const int lksel = (lane & 16) ? 8 : 0;

    auto compute = [&](int s){
        const uint32_t ao = (uint32_t)s * KSTG;
        #pragma unroll
        for (int ks = 0; ks < 4; ks++){
            const int kk = ks * 16 + lksel;
            uint32_t a[2][4];
            #pragma unroll
            for (int mi = 0; mi < 2; mi++)
                ldsm4(a[mi][0], a[mi][1], a[mi][2], a[mi][3],
                      sb + 2u * (ao + (wm + mi * 16 + lrow) * KAST + kk));
            uint32_t bq[4][4];
            #pragma unroll
            for (int nip = 0; nip < 4; nip++)
                ldsm4(bq[nip][0], bq[nip][1], bq[nip][2], bq[nip][3],
                      sb + 2u * (ao + KA_CH + (wn + nip * 16 + lrow) * KAST + kk));
            #pragma unroll
            for (int mi = 0; mi < 2; mi++)
                #pragma unroll
                for (int nip = 0; nip < 4; nip++){
                    mma_f16(cK[mi][2 * nip    ], a[mi], bq[nip][0], bq[nip][2]);
                    mma_f16(cK[mi][2 * nip + 1], a[mi], bq[nip][1], bq[nip][3]);
                }
            #pragma unroll
            for (int nip = 0; nip < 4; nip++)
                ldsm4(bq[nip][0], bq[nip][1], bq[nip][2], bq[nip][3],
                      sb + 2u * (ao + 2 * KA_CH + (wn + nip * 16 + lrow) * KAST + kk));
            #pragma unroll
            for (int mi = 0; mi < 2; mi++)
                #pragma unroll
                for (int nip = 0; nip < 4; nip++){
                    mma_f16(cV[mi][2 * nip    ], a[mi], bq[nip][0], bq[nip][2]);
                    mma_f16(cV[mi][2 * nip + 1], a[mi], bq[nip][1], bq[nip][3]);
                }
        }
    };

    load(0, 0); load(1, 1);
    #pragma unroll 1
    for (int c = 0; c < 8; c++){
        if (c < 7) { asm volatile("cp.async.wait_group 1;\n"); }
        else       { asm volatile("cp.async.wait_group 0;\n"); }
        __syncthreads();
        compute(c % 3);
        if (c < 6) load(c + 2, (c + 2) % 3);
    }

    int grows[4]; bool vals[4];
    const int r4 = lane >> 2;
    #pragma unroll
    for (int q = 0; q < 4; q++)
        maprow(g, t, wm + q * 8 + r4, grows[q], vals[q]);

    #pragma unroll
    for (int mi = 0; mi < 2; mi++){
        #pragma unroll
        for (int ni = 0; ni < 8; ni++){
            const int col = n0 + wn + ni * 8 + (lane & 3) * 2;
            const int q0 = mi * 2, q1 = mi * 2 + 1;
            if (vals[q0]){
                *reinterpret_cast<__half2*>(&g_K[(size_t)grows[q0] * DIM + col]) =
                    __floats2half2_rn(cK[mi][ni][0], cK[mi][ni][1]);
                *reinterpret_cast<__half2*>(&g_V[(size_t)grows[q0] * DIM + col]) =
                    __floats2half2_rn(cV[mi][ni][0], cV[mi][ni][1]);
            }
            if (vals[q1]){
                *reinterpret_cast<__half2*>(&g_K[(size_t)grows[q1] * DIM + col]) =
                    __floats2half2_rn(cK[mi][ni][2], cK[mi][ni][3]);
                *reinterpret_cast<__half2*>(&g_V[(size_t)grows[q1] * DIM + col]) =
                    __floats2half2_rn(cV[mi][ni][2], cV[mi][ni][3]);
            }
        }
    }
}

// ---------------- MMA attention ----------------
#define KST 72
#define PST 136
__global__ __launch_bounds__(128, 5)
void attn_kernel(int b0)
{
    const int h = blockIdx.x;
    const int b = blockIdx.y + b0;
    const int rowlim = b & (NLAT - 1);
    const int L  = rowlim + 1;
    const int Lk = ((rowlim >> 4) + 1) << 4;
    const int tid = threadIdx.x, lane = tid & 31, warp = tid >> 5;

    __shared__ __half Qs[NTOK * KST];
    __shared__ __half Ks[NLAT * KST];
    __shared__ __half Vs[NLAT * KST];
    __shared__ __half Ps[NTOK * PST];
    __shared__ float  Rinv[NTOK];

    {
        const int i = tid >> 3, c8 = (tid & 7) * 8;
        *reinterpret_cast<uint4*>(&Qs[i * KST + c8]) =
            *reinterpret_cast<const uint4*>(&g_Q[(size_t)(b * NTOK + i) * DIM + h * 64 + c8]);
    }
    for (int r0 = 0; r0 < Lk; r0 += 16){
        const int j = r0 + (tid >> 3), c8 = (tid & 7) * 8;
        const size_t g = (size_t)(b * NLAT + j) * DIM + h * 64 + c8;
        *reinterpret_cast<uint4*>(&Ks[j * KST + c8]) = *reinterpret_cast<const uint4*>(&g_K[g]);
        *reinterpret_cast<uint4*>(&Vs[j * KST + c8]) = *reinterpret_cast<const uint4*>(&g_V[g]);
    }
    __syncthreads();

    const uint32_t qb = (uint32_t)__cvta_generic_to_shared(Qs);
    const uint32_t kb = (uint32_t)__cvta_generic_to_shared(Ks);
    const uint32_t vb = (uint32_t)__cvta_generic_to_shared(Vs);
    const uint32_t pb = (uint32_t)__cvta_generic_to_shared(Ps);
    const int lrow  = (lane & 7) + ((lane >> 3) & 1) * 8;
    const int lksel = (lane & 16) ? 8 : 0;

    if (warp * 32 <= rowlim){
        uint32_t a[4][4];
        #pragma unroll
        for (int ks = 0; ks < 4; ks++)
            ldsm4(a[ks][0], a[ks][1], a[ks][2], a[ks][3],
                  qb + 2u * (lrow * KST + ks * 16 + lksel));

        #pragma unroll
        for (int sub = 0; sub < 2; sub++){
            const int jb = warp * 32 + sub * 16;
            if (jb > rowlim) break;
            float c0[4] = {0,0,0,0}, c1[4] = {0,0,0,0};
            #pragma unroll
            for (int ks = 0; ks < 4; ks++){
                uint32_t bbq[4];
                ldsm4(bbq[0], bbq[1], bbq[2], bbq[3],
                      kb + 2u * ((jb + lrow) * KST + ks * 16 + lksel));
                mma_f16(c0, a[ks], bbq[0], bbq[2]);
                mma_f16(c1, a[ks], bbq[1], bbq[3]);
            }
            const int r  = lane >> 2;
            const int cc = (lane & 3) * 2;
            #pragma unroll
            for (int t = 0; t < 2; t++){
                const float* cs = t ? c1 : c0;
                const int j0 = jb + t * 8 + cc;
                const float v0 = (j0     <= rowlim) ? cs[0] * 0.125f : 0.f;
                const float v1 = (j0 + 1 <= rowlim) ? cs[1] * 0.125f : 0.f;
                const float v2 = (j0     <= rowlim) ? cs[2] * 0.125f : 0.f;
                const float v3 = (j0 + 1 <= rowlim) ? cs[3] * 0.125f : 0.f;
                *reinterpret_cast<__half2*>(&Ps[r * PST + j0])       = __floats2half2_rn(v0, v1);
                *reinterpret_cast<__half2*>(&Ps[(r + 8) * PST + j0]) = __floats2half2_rn(v2, v3);
            }
        }
    }
    __syncthreads();

    for (int i = warp; i < NTOK; i += 4){
        float m = -1e30f;
        for (int jj = lane; jj < L; jj += 32) m = fmaxf(m, __half2float(Ps[i * PST + jj]));
        #pragma unroll
        for (int o = 16; o > 0; o >>= 1) m = fmaxf(m, __shfl_xor_sync(0xffffffffu, m, o));
        float sum = 0.f;
        for (int jj = lane; jj < L; jj += 32){
            const float e = __expf(__half2float(Ps[i * PST + jj]) - m);
            Ps[i * PST + jj] = __float2half(e);
            sum += e;
        }
        #pragma unroll
        for (int o = 16; o > 0; o >>= 1) sum += __shfl_xor_sync(0xffffffffu, sum, o);
        if (lane == 0) Rinv[i] = 1.f / sum;
    }
    __syncthreads();

    const int ksmax = (rowlim >> 4) + 1;
    float o0[4] = {0,0,0,0}, o1[4] = {0,0,0,0};
    #pragma unroll 1
    for (int ks = 0; ks < ksmax; ks++){
        const int jb = ks * 16;
        uint32_t ap[4], bv[4];
        ldsm4 (ap[0], ap[1], ap[2], ap[3], pb + 2u * (lrow * PST + jb + lksel));
        ldsm4t(bv[0], bv[1], bv[2], bv[3], vb + 2u * ((jb + lrow) * KST + warp * 16 + lksel));
        mma_f16(o0, ap, bv[0], bv[1]);
        mma_f16(o1, ap, bv[2], bv[3]);
    }
    {
        const int r  = lane >> 2;
        const int cc = (lane & 3) * 2;
        const float ri0 = Rinv[r], ri1 = Rinv[r + 8];
        __half2* A2 = reinterpret_cast<__half2*>(g_A);
        #pragma unroll
        for (int t = 0; t < 2; t++){
            const float* os = t ? o1 : o0;
            const int d = h * 64 + warp * 16 + t * 8 + cc;
            A2[((size_t)(b * NTOK + r)     * DIM + d) >> 1] = __floats2half2_rn(os[0] * ri0, os[1] * ri0);
            A2[((size_t)(b * NTOK + r + 8) * DIM + d) >> 1] = __floats2half2_rn(os[2] * ri1, os[3] * ri1);
        }
    }
}

extern "C" void kernel_launch(void* const* d_in, const int* in_sizes, int n_in,
                              void* d_out, int out_size)
{
    (void)in_sizes; (void)n_in; (void)out_size;
    const float* x  = (const float*)d_in[0];
    const float* l  = (const float*)d_in[1];
    const float* Wq = (const float*)d_in[2];
    const float* Wk = (const float*)d_in[3];
    const float* Wv = (const float*)d_in[4];
    const float* Wo = (const float*)d_in[5];
    const float* bo = (const float*)d_in[6];
    float* out = (float*)d_out;

    static cudaStream_t s1 = nullptr, s2 = nullptr;
    static cudaEvent_t eS, eW, eQ, eL0, eL1, eKV0, eKV1, eO0, eO1;
    static bool init_done = false;
    if (!init_done){
        cudaFuncSetAttribute(gemm512<0>, cudaFuncAttributeMaxDynamicSharedMemorySize, GEMM_SMEM_BYTES);
        cudaFuncSetAttribute(gemm512<3>, cudaFuncAttributeMaxDynamicSharedMemorySize, GEMM_SMEM_BYTES);
        cudaFuncSetAttribute(gemm_kv,   cudaFuncAttributeMaxDynamicSharedMemorySize, KV_SMEM_BYTES);
        cudaStreamCreateWithFlags(&s1, cudaStreamNonBlocking);
        cudaStreamCreateWithFlags(&s2, cudaStreamNonBlocking);
        cudaEventCreateWithFlags(&eS,   cudaEventDisableTiming);
        cudaEventCreateWithFlags(&eW,   cudaEventDisableTiming);
        cudaEventCreateWithFlags(&eQ,   cudaEventDisableTiming);
        cudaEventCreateWithFlags(&eL0,  cudaEventDisableTiming);
        cudaEventCreateWithFlags(&eL1,  cudaEventDisableTiming);
        cudaEventCreateWithFlags(&eKV0, cudaEventDisableTiming);
        cudaEventCreateWithFlags(&eKV1, cudaEventDisableTiming);
        cudaEventCreateWithFlags(&eO0,  cudaEventDisableTiming);
        cudaEventCreateWithFlags(&eO1,  cudaEventDisableTiming);
        init_done = true;
    }

    const int n4x = M_Q  * DIM / 4;
    const int n4l = M_KV * DIM / 4;
    const int n4l_half = n4l / 2;

    // fork side streams off the capture-origin (default) stream
    cudaEventRecord(eS, 0);
    cudaStreamWaitEvent(s1, eS, 0);
    cudaStreamWaitEvent(s2, eS, 0);

    // s1: weights + x staging, then Q projection
    f2h_w4<<<(4 * DIMDIM / 4 + 255) / 256, 256, 0, s1>>>(
        (const float4*)Wq, (const float4*)Wk, (const float4*)Wv, (const float4*)Wo);
    cudaEventRecord(eW, s1);
    f2h_x<<<(n4x + 255) / 256, 256, 0, s1>>>((const float4*)x);
    gemm512<0><<<dim3(DIM / BN, M_Q / BM), 128, GEMM_SMEM_BYTES, s1>>>(nullptr, nullptr, 0);
    cudaEventRecord(eQ, s1);

    // s0: l half 0
    f2h_l<<<(n4l_half + 255) / 256, 256>>>((const float4*)l, 0, n4l_half);
    cudaEventRecord(eL0, 0);

    // s2: l half 1 (after l half 0 to keep l0 on full bandwidth; overlaps KV0)
    cudaStreamWaitEvent(s2, eL0, 0);
    f2h_l<<<(n4l_half + 255) / 256, 256, 0, s2>>>((const float4*)l, n4l_half, n4l);
    cudaEventRecord(eL1, s2);

    // s0: KV groups 0-3 (needs W + l0), then KV groups 4-7 (needs l1)
    cudaStreamWaitEvent(0, eW, 0);
    gemm_kv<<<dim3(4, 260), 256, KV_SMEM_BYTES>>>(0);
    cudaEventRecord(eKV0, 0);
    cudaStreamWaitEvent(0, eL1, 0);
    gemm_kv<<<dim3(4, 260), 256, KV_SMEM_BYTES>>>(260);
    cudaEventRecord(eKV1, 0);

    // s1: attention + out-proj for batches 0-511 (needs Q [in-order] + KV0)
    cudaStreamWaitEvent(s1, eKV0, 0);
    attn_kernel<<<dim3(NH, NBATCH / 2), 128, 0, s1>>>(0);
    gemm512<3><<<dim3(DIM / BN, 128), 128, GEMM_SMEM_BYTES, s1>>>(bo, out, 0);
    cudaEventRecord(eO0, s1);

    // s2: attention + out-proj for batches 512-1023 (needs Q + KV1)
    cudaStreamWaitEvent(s2, eQ, 0);
    cudaStreamWaitEvent(s2, eKV1, 0);
    attn_kernel<<<dim3(NH, NBATCH / 2), 128, 0, s2>>>(NBATCH / 2);
    gemm512<3><<<dim3(DIM / BN, 128), 128, GEMM_SMEM_BYTES, s2>>>(bo, out, 128);
    cudaEventRecord(eO1, s2);

    // join everything back onto the origin stream
    cudaStreamWaitEvent(0, eO0, 0);
    cudaStreamWaitEvent(0, eO1, 0);
}